// round 10
// baseline (speedup 1.0000x reference)
#include <cuda_runtime.h>
#include <cuda_bf16.h>
#include <math_constants.h>
#include <cstdint>

// Problem constants
#define B_   1024
#define NTOK 68
#define C_   768
#define H_   12
#define HD   64
#define M_   (B_ * NTOK)        // 69632
#define K3C  (3 * C_)           // 2304

// Scratch (__device__ globals; allocation-free rule)
__device__ float         g_qkv[(size_t)M_ * K3C];   // QKV output fp32
__device__ __nv_bfloat16 g_xhi[(size_t)M_ * C_];    // x+pe split
__device__ __nv_bfloat16 g_xlo[(size_t)M_ * C_];
__device__ __nv_bfloat16 g_whi[(size_t)K3C * C_];   // w_qkv split
__device__ __nv_bfloat16 g_wlo[(size_t)K3C * C_];
__device__ __nv_bfloat16 g_phi[(size_t)C_ * C_];    // w_proj split
__device__ __nv_bfloat16 g_plo[(size_t)C_ * C_];
__device__ __nv_bfloat16 g_ahi[(size_t)M_ * C_];    // attention out split
__device__ __nv_bfloat16 g_alo[(size_t)M_ * C_];

// ---------------------------------------------------------------------------
// helpers
// ---------------------------------------------------------------------------
static __device__ __forceinline__ uint32_t smem_u32(const void* p) {
    uint32_t a;
    asm("{ .reg .u64 t; cvta.to.shared.u64 t, %1; cvt.u32.u64 %0, t; }"
        : "=r"(a) : "l"(p));
    return a;
}

static __device__ __forceinline__ void split2(float v, __nv_bfloat16& h,
                                              __nv_bfloat16& l) {
    h = __float2bfloat16_rn(v);
    l = __float2bfloat16_rn(v - __bfloat162float(h));
}

#define CP16(dst, src) \
    asm volatile("cp.async.cg.shared.global [%0], [%1], 16;" \
                 :: "r"(dst), "l"(src))
#define CP_COMMIT() asm volatile("cp.async.commit_group;" ::: "memory")
#define CP_WAIT2()  asm volatile("cp.async.wait_group 2;"  ::: "memory")

#define LDSM_X4(r, addr) \
    asm volatile("ldmatrix.sync.aligned.m8n8.x4.shared.b16 {%0,%1,%2,%3}, [%4];" \
                 : "=r"((r)[0]), "=r"((r)[1]), "=r"((r)[2]), "=r"((r)[3]) \
                 : "r"(addr))

#define MMA_BF16(d, a, b0, b1) \
    asm volatile("mma.sync.aligned.m16n8k16.row.col.f32.bf16.bf16.f32 " \
                 "{%0,%1,%2,%3}, {%4,%5,%6,%7}, {%8,%9}, {%0,%1,%2,%3};" \
                 : "+f"((d)[0]), "+f"((d)[1]), "+f"((d)[2]), "+f"((d)[3]) \
                 : "r"((a)[0]), "r"((a)[1]), "r"((a)[2]), "r"((a)[3]), \
                   "r"(b0), "r"(b1))

// smem tile: 128 rows x 64 bytes (32 bf16/row), XOR swizzle (conflict-free
// ldmatrix). 4 stages x 4 tiles (Ahi, Alo, Bhi, Blo) x 8KB = 128KB.
static __device__ __forceinline__ uint32_t sw_off(int row, int c) {
    const int s = (row & 3) ^ ((row >> 2) & 3);
    return (uint32_t)(row * 64 + ((c ^ s) << 4));
}
#define TILE_ST(s, w) ((s) * 32768 + (w) * 8192)
#define GEMM_SMEM 131072

// ---------------------------------------------------------------------------
// split kernels (fp32 -> bf16 hi/lo pair)
// ---------------------------------------------------------------------------
__global__ void split_x_pe_kernel(const float* __restrict__ x,
                                  const float* __restrict__ pe,
                                  __nv_bfloat16* __restrict__ hi,
                                  __nv_bfloat16* __restrict__ lo)
{
    const size_t i4 = (size_t)blockIdx.x * blockDim.x + threadIdx.x;
    const size_t e  = i4 * 4;
    if (e >= (size_t)M_ * C_) return;
    const int row = (int)(e / C_);
    const int col = (int)(e % C_);
    const int tok = row % NTOK;

    float4 v = *reinterpret_cast<const float4*>(x + e);
    if (tok >= 4) {
        const float4 p = *reinterpret_cast<const float4*>(
            pe + (size_t)(tok + 28) * C_ + col);
        v.x += p.x; v.y += p.y; v.z += p.z; v.w += p.w;
    }
    __nv_bfloat16 h0, l0, h1, l1, h2, l2, h3, l3;
    split2(v.x, h0, l0); split2(v.y, h1, l1);
    split2(v.z, h2, l2); split2(v.w, h3, l3);
    __nv_bfloat162* hp = reinterpret_cast<__nv_bfloat162*>(hi + e);
    __nv_bfloat162* lp = reinterpret_cast<__nv_bfloat162*>(lo + e);
    hp[0] = __nv_bfloat162(h0, h1); hp[1] = __nv_bfloat162(h2, h3);
    lp[0] = __nv_bfloat162(l0, l1); lp[1] = __nv_bfloat162(l2, l3);
}

__global__ void split_w_kernel(const float* __restrict__ w,
                               __nv_bfloat16* __restrict__ hi,
                               __nv_bfloat16* __restrict__ lo,
                               size_t n_elem)
{
    const size_t i4 = (size_t)blockIdx.x * blockDim.x + threadIdx.x;
    const size_t e  = i4 * 4;
    if (e >= n_elem) return;
    const float4 v = *reinterpret_cast<const float4*>(w + e);
    __nv_bfloat16 h0, l0, h1, l1, h2, l2, h3, l3;
    split2(v.x, h0, l0); split2(v.y, h1, l1);
    split2(v.z, h2, l2); split2(v.w, h3, l3);
    __nv_bfloat162* hp = reinterpret_cast<__nv_bfloat162*>(hi + e);
    __nv_bfloat162* lp = reinterpret_cast<__nv_bfloat162*>(lo + e);
    hp[0] = __nv_bfloat162(h0, h1); hp[1] = __nv_bfloat162(h2, h3);
    lp[0] = __nv_bfloat162(l0, l1); lp[1] = __nv_bfloat162(l2, l3);
}

// ---------------------------------------------------------------------------
// GEMM (round-5 best-measured config): C = A·W^T + bias with
// D = Ahi*Bhi + Ahi*Blo + Alo*Bhi  (bf16 mma.sync, fp32 accum).
// CTA 128x128, 256 threads / 8 warps (2m x 4n), warp tile 64x32, K-chunk 32,
// 4-stage cp.async ring, half-chunk register double-buffering, term-major MMA.
// ---------------------------------------------------------------------------
__global__ __launch_bounds__(256)
void gemm_bf16x3_kernel(const __nv_bfloat16* __restrict__ Ahi,
                        const __nv_bfloat16* __restrict__ Alo,
                        const __nv_bfloat16* __restrict__ Bhi,
                        const __nv_bfloat16* __restrict__ Blo,
                        const float* __restrict__ bias,
                        float* __restrict__ Cout,
                        int N, int K)
{
    extern __shared__ char smem[];
    const uint32_t sb = smem_u32(smem);

    const int tid  = threadIdx.x;
    const int wid  = tid >> 5;
    const int lane = tid & 31;
    const int cN   = blockIdx.x;
    const int cM   = blockIdx.y;
    const int wm   = wid & 1;    // 0..1
    const int wn   = wid >> 1;   // 0..3

    // ---- cp.async geometry: 2 x 16B per thread per tile ----
    const int r0 = tid >> 2,         c0 = tid & 3;
    const int r1 = (tid + 256) >> 2, c1 = (tid + 256) & 3;
    const uint32_t so0 = sw_off(r0, c0);
    const uint32_t so1 = sw_off(r1, c1);
    const __nv_bfloat16* gAh0 = Ahi + (size_t)(cM * 128 + r0) * K + c0 * 8;
    const __nv_bfloat16* gAh1 = Ahi + (size_t)(cM * 128 + r1) * K + c1 * 8;
    const __nv_bfloat16* gAl0 = Alo + (size_t)(cM * 128 + r0) * K + c0 * 8;
    const __nv_bfloat16* gAl1 = Alo + (size_t)(cM * 128 + r1) * K + c1 * 8;
    const __nv_bfloat16* gBh0 = Bhi + (size_t)(cN * 128 + r0) * K + c0 * 8;
    const __nv_bfloat16* gBh1 = Bhi + (size_t)(cN * 128 + r1) * K + c1 * 8;
    const __nv_bfloat16* gBl0 = Blo + (size_t)(cN * 128 + r0) * K + c0 * 8;
    const __nv_bfloat16* gBl1 = Blo + (size_t)(cN * 128 + r1) * K + c1 * 8;

#define LOAD_STAGE(s, k0)                                            \
    do {                                                              \
        CP16(sb + TILE_ST(s, 0) + so0, gAh0 + (k0));                  \
        CP16(sb + TILE_ST(s, 0) + so1, gAh1 + (k0));                  \
        CP16(sb + TILE_ST(s, 1) + so0, gAl0 + (k0));                  \
        CP16(sb + TILE_ST(s, 1) + so1, gAl1 + (k0));                  \
        CP16(sb + TILE_ST(s, 2) + so0, gBh0 + (k0));                  \
        CP16(sb + TILE_ST(s, 2) + so1, gBh1 + (k0));                  \
        CP16(sb + TILE_ST(s, 3) + so0, gBl0 + (k0));                  \
        CP16(sb + TILE_ST(s, 3) + so1, gBl1 + (k0));                  \
    } while (0)

    // per-warp ldmatrix base offsets
    const int arow = wm * 64 + (lane & 15);   // + mf*16
    const int brow = wn * 32 + (lane & 15);   // + bf*16
    const int chi  = lane >> 4;               // 16B column sub-chunk

#define FRAG_LOAD(Ah_, Al_, Bh_, Bl_, st, t)                                 \
    do {                                                                      \
        _Pragma("unroll")                                                     \
        for (int mf = 0; mf < 4; mf++) {                                      \
            const uint32_t ao = sw_off(arow + mf * 16, 2 * (t) + chi);        \
            LDSM_X4(Ah_[mf], sb + TILE_ST(st, 0) + ao);                       \
            LDSM_X4(Al_[mf], sb + TILE_ST(st, 1) + ao);                       \
        }                                                                     \
        _Pragma("unroll")                                                     \
        for (int bf = 0; bf < 2; bf++) {                                      \
            const uint32_t bo = sw_off(brow + bf * 16, 2 * (t) + chi);        \
            LDSM_X4(Bh_[bf], sb + TILE_ST(st, 2) + bo);                       \
            LDSM_X4(Bl_[bf], sb + TILE_ST(st, 3) + bo);                       \
        }                                                                     \
    } while (0)

// term-major: 3 passes of 16 independent-accumulator MMAs each
#define MMA_ALL(Ah_, Al_, Bh_, Bl_)                                          \
    do {                                                                      \
        _Pragma("unroll")                                                     \
        for (int mf = 0; mf < 4; mf++) {                                      \
            _Pragma("unroll")                                                 \
            for (int nf = 0; nf < 4; nf++) {                                  \
                const int g = nf >> 1, h = nf & 1;                            \
                MMA_BF16(acc[mf][nf], Ah_[mf], Bh_[g][h], Bh_[g][h + 2]);     \
            }                                                                 \
        }                                                                     \
        _Pragma("unroll")                                                     \
        for (int mf = 0; mf < 4; mf++) {                                      \
            _Pragma("unroll")                                                 \
            for (int nf = 0; nf < 4; nf++) {                                  \
                const int g = nf >> 1, h = nf & 1;                            \
                MMA_BF16(acc[mf][nf], Ah_[mf], Bl_[g][h], Bl_[g][h + 2]);     \
            }                                                                 \
        }                                                                     \
        _Pragma("unroll")                                                     \
        for (int mf = 0; mf < 4; mf++) {                                      \
            _Pragma("unroll")                                                 \
            for (int nf = 0; nf < 4; nf++) {                                  \
                const int g = nf >> 1, h = nf & 1;                            \
                MMA_BF16(acc[mf][nf], Al_[mf], Bh_[g][h], Bh_[g][h + 2]);     \
            }                                                                 \
        }                                                                     \
    } while (0)

    float acc[4][4][4];
#pragma unroll
    for (int i = 0; i < 4; i++)
#pragma unroll
        for (int j = 0; j < 4; j++)
#pragma unroll
            for (int r = 0; r < 4; r++) acc[i][j][r] = 0.0f;

    const int NC = K >> 5;   // 24

    // ---- prologue: 3 stages in flight ----
    LOAD_STAGE(0, 0);   CP_COMMIT();
    LOAD_STAGE(1, 32);  CP_COMMIT();
    LOAD_STAGE(2, 64);  CP_COMMIT();
    CP_WAIT2();
    __syncthreads();

    uint32_t Ah0[4][4], Al0[4][4], Bh0[2][4], Bl0[2][4];
    uint32_t Ah1[4][4], Al1[4][4], Bh1[2][4], Bl1[2][4];
    FRAG_LOAD(Ah0, Al0, Bh0, Bl0, 0, 0);

    for (int kc = 0; kc < NC; kc++) {
        const int cur = kc & 3;

        // prefetch second half of this chunk, then compute first half
        FRAG_LOAD(Ah1, Al1, Bh1, Bl1, cur, 1);
        MMA_ALL(Ah0, Al0, Bh0, Bl0);

        // keep the ring 3 ahead (slot (kc+3)&3 was freed last iteration)
        if (kc + 3 < NC) LOAD_STAGE((kc + 3) & 3, (kc + 3) * 32);
        CP_COMMIT();

        if (kc + 1 < NC) {
            CP_WAIT2();
            __syncthreads();
            // prefetch first half of next chunk, then compute second half
            FRAG_LOAD(Ah0, Al0, Bh0, Bl0, (kc + 1) & 3, 0);
        }
        MMA_ALL(Ah1, Al1, Bh1, Bl1);
    }

    // ---- epilogue: bias + fp32 store ----
#pragma unroll
    for (int mf = 0; mf < 4; mf++) {
        const int row = cM * 128 + wm * 64 + mf * 16 + (lane >> 2);
#pragma unroll
        for (int nf = 0; nf < 4; nf++) {
            const int col = cN * 128 + wn * 32 + nf * 8 + (lane & 3) * 2;
            const float2 bb = *reinterpret_cast<const float2*>(bias + col);
            float2 o0, o1;
            o0.x = acc[mf][nf][0] + bb.x;  o0.y = acc[mf][nf][1] + bb.y;
            o1.x = acc[mf][nf][2] + bb.x;  o1.y = acc[mf][nf][3] + bb.y;
            *reinterpret_cast<float2*>(Cout + (size_t)row * N + col) = o0;
            *reinterpret_cast<float2*>(Cout + (size_t)(row + 8) * N + col) = o1;
        }
    }
#undef LOAD_STAGE
#undef FRAG_LOAD
#undef MMA_ALL
}

// ---------------------------------------------------------------------------
// Attention: one CTA per (b, h); 4 q-rows per warp per iteration so the
// sk/sv smem loads amortize 4x (crossbar-bound kernel).
// Writes bf16 hi/lo split of output directly.
// ---------------------------------------------------------------------------
__global__ __launch_bounds__(256)
void attention_kernel(const float* __restrict__ qkv,
                      const float* __restrict__ mask,
                      __nv_bfloat16* __restrict__ ohi,
                      __nv_bfloat16* __restrict__ olo)
{
    __shared__ float sk[NTOK][HD + 1];
    __shared__ float sv[NTOK][HD + 1];
    __shared__ float sq[8][4][HD];
    __shared__ float sp[8][4][NTOK];

    const int bh = blockIdx.x;
    const int b  = bh / H_;
    const int h  = bh % H_;
    const int tid  = threadIdx.x;
    const int warp = tid >> 5;
    const int lane = tid & 31;

    const size_t base = (size_t)b * NTOK * K3C + (size_t)h * HD;
    for (int idx = tid; idx < NTOK * HD; idx += 256) {
        const int j = idx / HD, d = idx % HD;
        sk[j][d] = qkv[base + (size_t)j * K3C + C_ + d];
        sv[j][d] = qkv[base + (size_t)j * K3C + 2 * C_ + d];
    }
    __syncthreads();

    const float scale = 0.125f;
    const float* mrow_base = mask + (size_t)b * NTOK * NTOK;
    const int j0 = lane;
    const int j1 = lane + 32;
    const int j2 = (lane < 4) ? lane + 64 : 67;   // clamped; masked below

    // 17 groups of 4 rows
    for (int g = warp; g < 17; g += 8) {
        const int row0 = g * 4;

        // stage 4 scaled q rows
#pragma unroll
        for (int r = 0; r < 4; r++) {
            sq[warp][r][lane]      = qkv[base + (size_t)(row0 + r) * K3C + lane]      * scale;
            sq[warp][r][lane + 32] = qkv[base + (size_t)(row0 + r) * K3C + lane + 32] * scale;
        }
        __syncwarp();

        // scores: 4 rows x 3 key slots; sk loads shared across the 4 rows
        float s[4][3];
#pragma unroll
        for (int r = 0; r < 4; r++)
            s[r][0] = s[r][1] = s[r][2] = 0.0f;

#pragma unroll
        for (int d = 0; d < HD; d++) {
            const float k0 = sk[j0][d];
            const float k1 = sk[j1][d];
            const float k2 = sk[j2][d];
#pragma unroll
            for (int r = 0; r < 4; r++) {
                const float q = sq[warp][r][d];
                s[r][0] = fmaf(q, k0, s[r][0]);
                s[r][1] = fmaf(q, k1, s[r][1]);
                s[r][2] = fmaf(q, k2, s[r][2]);
            }
        }

        // add mask; invalidate clamped j2 lanes
#pragma unroll
        for (int r = 0; r < 4; r++) {
            const float* mrow = mrow_base + (size_t)(row0 + r) * NTOK;
            s[r][0] += mrow[j0];
            s[r][1] += mrow[j1];
            s[r][2] = (lane < 4) ? (s[r][2] + mrow[j2]) : -CUDART_INF_F;
        }

        // softmax per row
#pragma unroll
        for (int r = 0; r < 4; r++) {
            float mx = fmaxf(fmaxf(s[r][0], s[r][1]), s[r][2]);
#pragma unroll
            for (int off = 16; off > 0; off >>= 1)
                mx = fmaxf(mx, __shfl_xor_sync(0xffffffffu, mx, off));

            const float e0 = __expf(s[r][0] - mx);
            const float e1 = __expf(s[r][1] - mx);
            const float e2 = (lane < 4) ? __expf(s[r][2] - mx) : 0.0f;
            float sum = e0 + e1 + e2;
#pragma unroll
            for (int off = 16; off > 0; off >>= 1)
                sum += __shfl_xor_sync(0xffffffffu, sum, off);
            const float inv = 1.0f / sum;

            sp[warp][r][j0] = e0 * inv;
            sp[warp][r][j1] = e1 * inv;
            if (lane < 4) sp[warp][r][j2] = e2 * inv;
        }
        __syncwarp();

        // PV: sv loads shared across the 4 rows
        float o[4][2];
#pragma unroll
        for (int r = 0; r < 4; r++) o[r][0] = o[r][1] = 0.0f;

#pragma unroll
        for (int j = 0; j < NTOK; j++) {
            const float v0 = sv[j][lane];
            const float v1 = sv[j][lane + 32];
#pragma unroll
            for (int r = 0; r < 4; r++) {
                const float p = sp[warp][r][j];
                o[r][0] = fmaf(p, v0, o[r][0]);
                o[r][1] = fmaf(p, v1, o[r][1]);
            }
        }

#pragma unroll
        for (int r = 0; r < 4; r++) {
            const size_t obase = ((size_t)b * NTOK + row0 + r) * C_ + (size_t)h * HD;
            __nv_bfloat16 hh, ll;
            split2(o[r][0], hh, ll);
            ohi[obase + lane]      = hh;  olo[obase + lane]      = ll;
            split2(o[r][1], hh, ll);
            ohi[obase + lane + 32] = hh;  olo[obase + lane + 32] = ll;
        }
        __syncwarp();
    }
}

// ---------------------------------------------------------------------------
extern "C" void kernel_launch(void* const* d_in, const int* in_sizes, int n_in,
                              void* d_out, int out_size)
{
    const float* x      = (const float*)d_in[0];
    const float* pe     = (const float*)d_in[1];
    const float* mask   = (const float*)d_in[2];
    const float* w_qkv  = (const float*)d_in[3];
    const float* b_qkv  = (const float*)d_in[4];
    const float* w_proj = (const float*)d_in[5];
    const float* b_proj = (const float*)d_in[6];
    float* out = (float*)d_out;

    float*         qkv_buf; cudaGetSymbolAddress((void**)&qkv_buf, g_qkv);
    __nv_bfloat16 *xhi, *xlo, *whi, *wlo, *phi, *plo, *ahi, *alo;
    cudaGetSymbolAddress((void**)&xhi, g_xhi);
    cudaGetSymbolAddress((void**)&xlo, g_xlo);
    cudaGetSymbolAddress((void**)&whi, g_whi);
    cudaGetSymbolAddress((void**)&wlo, g_wlo);
    cudaGetSymbolAddress((void**)&phi, g_phi);
    cudaGetSymbolAddress((void**)&plo, g_plo);
    cudaGetSymbolAddress((void**)&ahi, g_ahi);
    cudaGetSymbolAddress((void**)&alo, g_alo);

    cudaFuncSetAttribute(gemm_bf16x3_kernel,
                         cudaFuncAttributeMaxDynamicSharedMemorySize, GEMM_SMEM);

    // 0) precompute bf16 splits
    {
        const size_t nx = (size_t)M_ * C_ / 4;
        split_x_pe_kernel<<<(unsigned)((nx + 255) / 256), 256>>>(x, pe, xhi, xlo);
        const size_t nw = (size_t)K3C * C_;
        split_w_kernel<<<(unsigned)((nw / 4 + 255) / 256), 256>>>(w_qkv, whi, wlo, nw);
        const size_t np = (size_t)C_ * C_;
        split_w_kernel<<<(unsigned)((np / 4 + 255) / 256), 256>>>(w_proj, phi, plo, np);
    }

    // 1) QKV projection: (M x 768) @ (768 x 2304)^T + bias -> g_qkv (fp32)
    {
        dim3 grid(K3C / 128, M_ / 128);
        gemm_bf16x3_kernel<<<grid, 256, GEMM_SMEM>>>(xhi, xlo, whi, wlo,
                                                     b_qkv, qkv_buf, K3C, C_);
    }

    // 2) Attention -> bf16 split output
    attention_kernel<<<B_ * H_, 256>>>(qkv_buf, mask, ahi, alo);

    // 3) Output projection -> d_out
    {
        dim3 grid(C_ / 128, M_ / 128);
        gemm_bf16x3_kernel<<<grid, 256, GEMM_SMEM>>>(ahi, alo, phi, plo,
                                                     b_proj, out, C_, C_);
    }
}

// round 11
// speedup vs baseline: 1.5171x; 1.5171x over previous
#include <cuda_runtime.h>
#include <cuda_bf16.h>
#include <math_constants.h>
#include <cstdint>

// Problem constants
#define B_   1024
#define NTOK 68
#define C_   768
#define H_   12
#define HD   64
#define M_   (B_ * NTOK)        // 69632
#define K3C  (3 * C_)           // 2304

// Scratch (__device__ globals; allocation-free rule)
__device__ float         g_qkv[(size_t)M_ * K3C];   // QKV output fp32
__device__ __nv_bfloat16 g_xhi[(size_t)M_ * C_];    // x+pe split
__device__ __nv_bfloat16 g_xlo[(size_t)M_ * C_];
__device__ __nv_bfloat16 g_whi[(size_t)K3C * C_];   // w_qkv split
__device__ __nv_bfloat16 g_wlo[(size_t)K3C * C_];
__device__ __nv_bfloat16 g_phi[(size_t)C_ * C_];    // w_proj split
__device__ __nv_bfloat16 g_plo[(size_t)C_ * C_];
__device__ __nv_bfloat16 g_ahi[(size_t)M_ * C_];    // attention out split
__device__ __nv_bfloat16 g_alo[(size_t)M_ * C_];

// ---------------------------------------------------------------------------
// helpers
// ---------------------------------------------------------------------------
static __device__ __forceinline__ uint32_t smem_u32(const void* p) {
    uint32_t a;
    asm("{ .reg .u64 t; cvta.to.shared.u64 t, %1; cvt.u32.u64 %0, t; }"
        : "=r"(a) : "l"(p));
    return a;
}

static __device__ __forceinline__ void split2(float v, __nv_bfloat16& h,
                                              __nv_bfloat16& l) {
    h = __float2bfloat16_rn(v);
    l = __float2bfloat16_rn(v - __bfloat162float(h));
}

#define CP16(dst, src) \
    asm volatile("cp.async.cg.shared.global [%0], [%1], 16;" \
                 :: "r"(dst), "l"(src))
#define CP_COMMIT() asm volatile("cp.async.commit_group;" ::: "memory")
#define CP_WAIT2()  asm volatile("cp.async.wait_group 2;"  ::: "memory")

#define LDSM_X4(r, addr) \
    asm volatile("ldmatrix.sync.aligned.m8n8.x4.shared.b16 {%0,%1,%2,%3}, [%4];" \
                 : "=r"((r)[0]), "=r"((r)[1]), "=r"((r)[2]), "=r"((r)[3]) \
                 : "r"(addr))

#define MMA_BF16(d, a, b0, b1) \
    asm volatile("mma.sync.aligned.m16n8k16.row.col.f32.bf16.bf16.f32 " \
                 "{%0,%1,%2,%3}, {%4,%5,%6,%7}, {%8,%9}, {%0,%1,%2,%3};" \
                 : "+f"((d)[0]), "+f"((d)[1]), "+f"((d)[2]), "+f"((d)[3]) \
                 : "r"((a)[0]), "r"((a)[1]), "r"((a)[2]), "r"((a)[3]), \
                   "r"(b0), "r"(b1))

// smem tile: 128 rows x 64 bytes (32 bf16/row), XOR swizzle (conflict-free
// ldmatrix). 4 stages x 4 tiles (Ahi, Alo, Bhi, Blo) x 8KB = 128KB.
static __device__ __forceinline__ uint32_t sw_off(int row, int c) {
    const int s = (row & 3) ^ ((row >> 2) & 3);
    return (uint32_t)(row * 64 + ((c ^ s) << 4));
}
#define TILE_ST(s, w) ((s) * 32768 + (w) * 8192)
#define GEMM_SMEM 131072
#define GEMM_GRID 592

// ---------------------------------------------------------------------------
// split kernels (fp32 -> bf16 hi/lo pair)
// ---------------------------------------------------------------------------
__global__ void split_x_pe_kernel(const float* __restrict__ x,
                                  const float* __restrict__ pe,
                                  __nv_bfloat16* __restrict__ hi,
                                  __nv_bfloat16* __restrict__ lo)
{
    const size_t i4 = (size_t)blockIdx.x * blockDim.x + threadIdx.x;
    const size_t e  = i4 * 4;
    if (e >= (size_t)M_ * C_) return;
    const int row = (int)(e / C_);
    const int col = (int)(e % C_);
    const int tok = row % NTOK;

    float4 v = *reinterpret_cast<const float4*>(x + e);
    if (tok >= 4) {
        const float4 p = *reinterpret_cast<const float4*>(
            pe + (size_t)(tok + 28) * C_ + col);
        v.x += p.x; v.y += p.y; v.z += p.z; v.w += p.w;
    }
    __nv_bfloat16 h0, l0, h1, l1, h2, l2, h3, l3;
    split2(v.x, h0, l0); split2(v.y, h1, l1);
    split2(v.z, h2, l2); split2(v.w, h3, l3);
    __nv_bfloat162* hp = reinterpret_cast<__nv_bfloat162*>(hi + e);
    __nv_bfloat162* lp = reinterpret_cast<__nv_bfloat162*>(lo + e);
    hp[0] = __nv_bfloat162(h0, h1); hp[1] = __nv_bfloat162(h2, h3);
    lp[0] = __nv_bfloat162(l0, l1); lp[1] = __nv_bfloat162(l2, l3);
}

__global__ void split_w_kernel(const float* __restrict__ w,
                               __nv_bfloat16* __restrict__ hi,
                               __nv_bfloat16* __restrict__ lo,
                               size_t n_elem)
{
    const size_t i4 = (size_t)blockIdx.x * blockDim.x + threadIdx.x;
    const size_t e  = i4 * 4;
    if (e >= n_elem) return;
    const float4 v = *reinterpret_cast<const float4*>(w + e);
    __nv_bfloat16 h0, l0, h1, l1, h2, l2, h3, l3;
    split2(v.x, h0, l0); split2(v.y, h1, l1);
    split2(v.z, h2, l2); split2(v.w, h3, l3);
    __nv_bfloat162* hp = reinterpret_cast<__nv_bfloat162*>(hi + e);
    __nv_bfloat162* lp = reinterpret_cast<__nv_bfloat162*>(lo + e);
    hp[0] = __nv_bfloat162(h0, h1); hp[1] = __nv_bfloat162(h2, h3);
    lp[0] = __nv_bfloat162(l0, l1); lp[1] = __nv_bfloat162(l2, l3);
}

// ---------------------------------------------------------------------------
// Persistent GEMM: C = A·W^T + bias, D = Ahi*Bhi + Ahi*Blo + Alo*Bhi.
// R5 mainloop (CTA 128x128, 8 warps 2m x 4n, warp tile 64x32, K-chunk 32,
// 4-stage ring, half-chunk frag double-buffer, term-major MMA) wrapped in a
// grid-stride tile loop: the cp.async ring runs CONTINUOUSLY across tile
// boundaries (last 3 refills of tile t prefetch chunks 0-2 of tile t+stride),
// so the pipeline-fill cost is paid once per ~16 tiles instead of per tile.
// NC = K/32 must be divisible by 4 (768/32 = 24 ok) to keep slot phase.
// ---------------------------------------------------------------------------
__global__ __launch_bounds__(256)
void gemm_bf16x3_kernel(const __nv_bfloat16* __restrict__ Ahi,
                        const __nv_bfloat16* __restrict__ Alo,
                        const __nv_bfloat16* __restrict__ Bhi,
                        const __nv_bfloat16* __restrict__ Blo,
                        const float* __restrict__ bias,
                        float* __restrict__ Cout,
                        int N, int K, int NT, int TT)
{
    extern __shared__ char smem[];
    const uint32_t sb = smem_u32(smem);

    const int tid  = threadIdx.x;
    const int wid  = tid >> 5;
    const int lane = tid & 31;
    const int wm   = wid & 1;    // 0..1
    const int wn   = wid >> 1;   // 0..3

    // ---- cp.async geometry: 2 x 16B per thread per tile ----
    const int r0 = tid >> 2,         c0 = tid & 3;
    const int r1 = (tid + 256) >> 2, c1 = (tid + 256) & 3;
    const uint32_t so0 = sw_off(r0, c0);
    const uint32_t so1 = sw_off(r1, c1);

#define TILE_OFFSETS(lt_, a0_, a1_, b0_, b1_)                         \
    do {                                                              \
        const int cN_ = (lt_) % NT, cM_ = (lt_) / NT;                 \
        a0_ = (size_t)(cM_ * 128 + r0) * K + c0 * 8;                  \
        a1_ = (size_t)(cM_ * 128 + r1) * K + c1 * 8;                  \
        b0_ = (size_t)(cN_ * 128 + r0) * K + c0 * 8;                  \
        b1_ = (size_t)(cN_ * 128 + r1) * K + c1 * 8;                  \
    } while (0)

#define LOAD_STAGE(s, a0_, a1_, b0_, b1_, k0)                         \
    do {                                                              \
        CP16(sb + TILE_ST(s, 0) + so0, Ahi + (a0_) + (k0));           \
        CP16(sb + TILE_ST(s, 0) + so1, Ahi + (a1_) + (k0));           \
        CP16(sb + TILE_ST(s, 1) + so0, Alo + (a0_) + (k0));           \
        CP16(sb + TILE_ST(s, 1) + so1, Alo + (a1_) + (k0));           \
        CP16(sb + TILE_ST(s, 2) + so0, Bhi + (b0_) + (k0));           \
        CP16(sb + TILE_ST(s, 2) + so1, Bhi + (b1_) + (k0));           \
        CP16(sb + TILE_ST(s, 3) + so0, Blo + (b0_) + (k0));           \
        CP16(sb + TILE_ST(s, 3) + so1, Blo + (b1_) + (k0));           \
    } while (0)

    // per-warp ldmatrix base offsets
    const int arow = wm * 64 + (lane & 15);   // + mf*16
    const int brow = wn * 32 + (lane & 15);   // + bf*16
    const int chi  = lane >> 4;               // 16B column sub-chunk

#define FRAG_LOAD(Ah_, Al_, Bh_, Bl_, st, t)                                 \
    do {                                                                      \
        _Pragma("unroll")                                                     \
        for (int mf = 0; mf < 4; mf++) {                                      \
            const uint32_t ao = sw_off(arow + mf * 16, 2 * (t) + chi);        \
            LDSM_X4(Ah_[mf], sb + TILE_ST(st, 0) + ao);                       \
            LDSM_X4(Al_[mf], sb + TILE_ST(st, 1) + ao);                       \
        }                                                                     \
        _Pragma("unroll")                                                     \
        for (int bf = 0; bf < 2; bf++) {                                      \
            const uint32_t bo = sw_off(brow + bf * 16, 2 * (t) + chi);        \
            LDSM_X4(Bh_[bf], sb + TILE_ST(st, 2) + bo);                       \
            LDSM_X4(Bl_[bf], sb + TILE_ST(st, 3) + bo);                       \
        }                                                                     \
    } while (0)

// term-major: 3 passes of 16 independent-accumulator MMAs each
#define MMA_ALL(Ah_, Al_, Bh_, Bl_)                                          \
    do {                                                                      \
        _Pragma("unroll")                                                     \
        for (int mf = 0; mf < 4; mf++) {                                      \
            _Pragma("unroll")                                                 \
            for (int nf = 0; nf < 4; nf++) {                                  \
                const int g = nf >> 1, h = nf & 1;                            \
                MMA_BF16(acc[mf][nf], Ah_[mf], Bh_[g][h], Bh_[g][h + 2]);     \
            }                                                                 \
        }                                                                     \
        _Pragma("unroll")                                                     \
        for (int mf = 0; mf < 4; mf++) {                                      \
            _Pragma("unroll")                                                 \
            for (int nf = 0; nf < 4; nf++) {                                  \
                const int g = nf >> 1, h = nf & 1;                            \
                MMA_BF16(acc[mf][nf], Ah_[mf], Bl_[g][h], Bl_[g][h + 2]);     \
            }                                                                 \
        }                                                                     \
        _Pragma("unroll")                                                     \
        for (int mf = 0; mf < 4; mf++) {                                      \
            _Pragma("unroll")                                                 \
            for (int nf = 0; nf < 4; nf++) {                                  \
                const int g = nf >> 1, h = nf & 1;                            \
                MMA_BF16(acc[mf][nf], Al_[mf], Bh_[g][h], Bh_[g][h + 2]);     \
            }                                                                 \
        }                                                                     \
    } while (0)

    float acc[4][4][4];
#pragma unroll
    for (int i = 0; i < 4; i++)
#pragma unroll
        for (int j = 0; j < 4; j++)
#pragma unroll
            for (int r = 0; r < 4; r++) acc[i][j][r] = 0.0f;

    const int NC = K >> 5;   // 24 (divisible by 4)

    uint32_t Ah0[4][4], Al0[4][4], Bh0[2][4], Bl0[2][4];
    uint32_t Ah1[4][4], Al1[4][4], Bh1[2][4], Bl1[2][4];

    int lt = blockIdx.x;
    if (lt >= TT) return;

    size_t a0, a1, b0, b1;
    TILE_OFFSETS(lt, a0, a1, b0, b1);

    // ---- prologue: 3 stages in flight, first half-chunk fragments loaded ----
    LOAD_STAGE(0, a0, a1, b0, b1, 0);   CP_COMMIT();
    LOAD_STAGE(1, a0, a1, b0, b1, 32);  CP_COMMIT();
    LOAD_STAGE(2, a0, a1, b0, b1, 64);  CP_COMMIT();
    CP_WAIT2();
    __syncthreads();
    FRAG_LOAD(Ah0, Al0, Bh0, Bl0, 0, 0);

    for (;;) {
        const int  ltn       = lt + (int)gridDim.x;
        const bool have_next = ltn < TT;
        size_t na0 = 0, na1 = 0, nb0 = 0, nb1 = 0;
        if (have_next) TILE_OFFSETS(ltn, na0, na1, nb0, nb1);

        for (int kc = 0; kc < NC; kc++) {
            const int cur = kc & 3;

            // prefetch second half of this chunk, then compute first half
            FRAG_LOAD(Ah1, Al1, Bh1, Bl1, cur, 1);
            MMA_ALL(Ah0, Al0, Bh0, Bl0);

            // refill slot freed last iteration; cross tile boundary if needed
            const int rc = kc + 3;
            if (rc < NC) {
                LOAD_STAGE(rc & 3, a0, a1, b0, b1, rc * 32);
            } else if (have_next) {
                LOAD_STAGE(rc & 3, na0, na1, nb0, nb1, (rc - NC) * 32);
            }
            CP_COMMIT();

            if (kc + 1 < NC) {
                CP_WAIT2();
                __syncthreads();
                FRAG_LOAD(Ah0, Al0, Bh0, Bl0, (kc + 1) & 3, 0);
            }
            MMA_ALL(Ah1, Al1, Bh1, Bl1);
        }

        // ---- epilogue for tile lt: bias + fp32 store (overlaps next loads) --
        {
            const int cN = lt % NT, cM = lt / NT;
#pragma unroll
            for (int mf = 0; mf < 4; mf++) {
                const int row = cM * 128 + wm * 64 + mf * 16 + (lane >> 2);
#pragma unroll
                for (int nf = 0; nf < 4; nf++) {
                    const int col = cN * 128 + wn * 32 + nf * 8 + (lane & 3) * 2;
                    const float2 bb = *reinterpret_cast<const float2*>(bias + col);
                    float2 o0, o1;
                    o0.x = acc[mf][nf][0] + bb.x;  o0.y = acc[mf][nf][1] + bb.y;
                    o1.x = acc[mf][nf][2] + bb.x;  o1.y = acc[mf][nf][3] + bb.y;
                    *reinterpret_cast<float2*>(Cout + (size_t)row * N + col) = o0;
                    *reinterpret_cast<float2*>(Cout + (size_t)(row + 8) * N + col) = o1;
                }
            }
        }
#pragma unroll
        for (int i = 0; i < 4; i++)
#pragma unroll
            for (int j = 0; j < 4; j++)
#pragma unroll
                for (int r = 0; r < 4; r++) acc[i][j][r] = 0.0f;

        if (!have_next) break;
        lt = ltn;
        a0 = na0; a1 = na1; b0 = nb0; b1 = nb1;

        // chunk 0 of the new tile (slot 0, loaded 3 refills ago)
        CP_WAIT2();
        __syncthreads();
        FRAG_LOAD(Ah0, Al0, Bh0, Bl0, 0, 0);
    }
#undef TILE_OFFSETS
#undef LOAD_STAGE
#undef FRAG_LOAD
#undef MMA_ALL
}

// ---------------------------------------------------------------------------
// Attention: one CTA per (b, h); 4 q-rows per warp per iteration so the
// sk/sv smem loads amortize 4x (crossbar-bound kernel).
// Writes bf16 hi/lo split of output directly.
// ---------------------------------------------------------------------------
__global__ __launch_bounds__(256)
void attention_kernel(const float* __restrict__ qkv,
                      const float* __restrict__ mask,
                      __nv_bfloat16* __restrict__ ohi,
                      __nv_bfloat16* __restrict__ olo)
{
    __shared__ float sk[NTOK][HD + 1];
    __shared__ float sv[NTOK][HD + 1];
    __shared__ float sq[8][4][HD];
    __shared__ float sp[8][4][NTOK];

    const int bh = blockIdx.x;
    const int b  = bh / H_;
    const int h  = bh % H_;
    const int tid  = threadIdx.x;
    const int warp = tid >> 5;
    const int lane = tid & 31;

    const size_t base = (size_t)b * NTOK * K3C + (size_t)h * HD;
    for (int idx = tid; idx < NTOK * HD; idx += 256) {
        const int j = idx / HD, d = idx % HD;
        sk[j][d] = qkv[base + (size_t)j * K3C + C_ + d];
        sv[j][d] = qkv[base + (size_t)j * K3C + 2 * C_ + d];
    }
    __syncthreads();

    const float scale = 0.125f;
    const float* mrow_base = mask + (size_t)b * NTOK * NTOK;
    const int j0 = lane;
    const int j1 = lane + 32;
    const int j2 = (lane < 4) ? lane + 64 : 67;   // clamped; masked below

    // 17 groups of 4 rows
    for (int g = warp; g < 17; g += 8) {
        const int row0 = g * 4;

        // stage 4 scaled q rows
#pragma unroll
        for (int r = 0; r < 4; r++) {
            sq[warp][r][lane]      = qkv[base + (size_t)(row0 + r) * K3C + lane]      * scale;
            sq[warp][r][lane + 32] = qkv[base + (size_t)(row0 + r) * K3C + lane + 32] * scale;
        }
        __syncwarp();

        // scores: 4 rows x 3 key slots; sk loads shared across the 4 rows
        float s[4][3];
#pragma unroll
        for (int r = 0; r < 4; r++)
            s[r][0] = s[r][1] = s[r][2] = 0.0f;

#pragma unroll
        for (int d = 0; d < HD; d++) {
            const float k0 = sk[j0][d];
            const float k1 = sk[j1][d];
            const float k2 = sk[j2][d];
#pragma unroll
            for (int r = 0; r < 4; r++) {
                const float q = sq[warp][r][d];
                s[r][0] = fmaf(q, k0, s[r][0]);
                s[r][1] = fmaf(q, k1, s[r][1]);
                s[r][2] = fmaf(q, k2, s[r][2]);
            }
        }

        // add mask; invalidate clamped j2 lanes
#pragma unroll
        for (int r = 0; r < 4; r++) {
            const float* mrow = mrow_base + (size_t)(row0 + r) * NTOK;
            s[r][0] += mrow[j0];
            s[r][1] += mrow[j1];
            s[r][2] = (lane < 4) ? (s[r][2] + mrow[j2]) : -CUDART_INF_F;
        }

        // softmax per row
#pragma unroll
        for (int r = 0; r < 4; r++) {
            float mx = fmaxf(fmaxf(s[r][0], s[r][1]), s[r][2]);
#pragma unroll
            for (int off = 16; off > 0; off >>= 1)
                mx = fmaxf(mx, __shfl_xor_sync(0xffffffffu, mx, off));

            const float e0 = __expf(s[r][0] - mx);
            const float e1 = __expf(s[r][1] - mx);
            const float e2 = (lane < 4) ? __expf(s[r][2] - mx) : 0.0f;
            float sum = e0 + e1 + e2;
#pragma unroll
            for (int off = 16; off > 0; off >>= 1)
                sum += __shfl_xor_sync(0xffffffffu, sum, off);
            const float inv = 1.0f / sum;

            sp[warp][r][j0] = e0 * inv;
            sp[warp][r][j1] = e1 * inv;
            if (lane < 4) sp[warp][r][j2] = e2 * inv;
        }
        __syncwarp();

        // PV: sv loads shared across the 4 rows
        float o[4][2];
#pragma unroll
        for (int r = 0; r < 4; r++) o[r][0] = o[r][1] = 0.0f;

#pragma unroll
        for (int j = 0; j < NTOK; j++) {
            const float v0 = sv[j][lane];
            const float v1 = sv[j][lane + 32];
#pragma unroll
            for (int r = 0; r < 4; r++) {
                const float p = sp[warp][r][j];
                o[r][0] = fmaf(p, v0, o[r][0]);
                o[r][1] = fmaf(p, v1, o[r][1]);
            }
        }

#pragma unroll
        for (int r = 0; r < 4; r++) {
            const size_t obase = ((size_t)b * NTOK + row0 + r) * C_ + (size_t)h * HD;
            __nv_bfloat16 hh, ll;
            split2(o[r][0], hh, ll);
            ohi[obase + lane]      = hh;  olo[obase + lane]      = ll;
            split2(o[r][1], hh, ll);
            ohi[obase + lane + 32] = hh;  olo[obase + lane + 32] = ll;
        }
        __syncwarp();
    }
}

// ---------------------------------------------------------------------------
extern "C" void kernel_launch(void* const* d_in, const int* in_sizes, int n_in,
                              void* d_out, int out_size)
{
    const float* x      = (const float*)d_in[0];
    const float* pe     = (const float*)d_in[1];
    const float* mask   = (const float*)d_in[2];
    const float* w_qkv  = (const float*)d_in[3];
    const float* b_qkv  = (const float*)d_in[4];
    const float* w_proj = (const float*)d_in[5];
    const float* b_proj = (const float*)d_in[6];
    float* out = (float*)d_out;

    float*         qkv_buf; cudaGetSymbolAddress((void**)&qkv_buf, g_qkv);
    __nv_bfloat16 *xhi, *xlo, *whi, *wlo, *phi, *plo, *ahi, *alo;
    cudaGetSymbolAddress((void**)&xhi, g_xhi);
    cudaGetSymbolAddress((void**)&xlo, g_xlo);
    cudaGetSymbolAddress((void**)&whi, g_whi);
    cudaGetSymbolAddress((void**)&wlo, g_wlo);
    cudaGetSymbolAddress((void**)&phi, g_phi);
    cudaGetSymbolAddress((void**)&plo, g_plo);
    cudaGetSymbolAddress((void**)&ahi, g_ahi);
    cudaGetSymbolAddress((void**)&alo, g_alo);

    cudaFuncSetAttribute(gemm_bf16x3_kernel,
                         cudaFuncAttributeMaxDynamicSharedMemorySize, GEMM_SMEM);

    // 0) precompute bf16 splits
    {
        const size_t nx = (size_t)M_ * C_ / 4;
        split_x_pe_kernel<<<(unsigned)((nx + 255) / 256), 256>>>(x, pe, xhi, xlo);
        const size_t nw = (size_t)K3C * C_;
        split_w_kernel<<<(unsigned)((nw / 4 + 255) / 256), 256>>>(w_qkv, whi, wlo, nw);
        const size_t np = (size_t)C_ * C_;
        split_w_kernel<<<(unsigned)((np / 4 + 255) / 256), 256>>>(w_proj, phi, plo, np);
    }

    // 1) QKV projection: (M x 768) @ (768 x 2304)^T + bias -> g_qkv (fp32)
    {
        const int NT = K3C / 128;           // 18
        const int TT = (M_ / 128) * NT;     // 9792
        gemm_bf16x3_kernel<<<GEMM_GRID, 256, GEMM_SMEM>>>(
            xhi, xlo, whi, wlo, b_qkv, qkv_buf, K3C, C_, NT, TT);
    }

    // 2) Attention -> bf16 split output
    attention_kernel<<<B_ * H_, 256>>>(qkv_buf, mask, ahi, alo);

    // 3) Output projection -> d_out
    {
        const int NT = C_ / 128;            // 6
        const int TT = (M_ / 128) * NT;     // 4080
        gemm_bf16x3_kernel<<<GEMM_GRID, 256, GEMM_SMEM>>>(
            ahi, alo, phi, plo, b_proj, out, C_, C_, NT, TT);
    }
}

// round 12
// speedup vs baseline: 1.8547x; 1.2226x over previous
#include <cuda_runtime.h>
#include <cuda_fp16.h>
#include <math_constants.h>
#include <cstdint>

// Problem constants
#define B_   1024
#define NTOK 68
#define C_   768
#define H_   12
#define HD   64
#define M_   (B_ * NTOK)        // 69632
#define K3C  (3 * C_)           // 2304

// Scratch (__device__ globals; allocation-free rule)
__device__ float  g_qkv[(size_t)M_ * K3C];   // QKV output fp32
__device__ __half g_xa [(size_t)M_ * C_];    // x+pe, single fp16
__device__ __half g_whi[(size_t)K3C * C_];   // w_qkv split hi
__device__ __half g_wlo[(size_t)K3C * C_];   // w_qkv split lo
__device__ __half g_phi[(size_t)C_ * C_];    // w_proj split hi
__device__ __half g_plo[(size_t)C_ * C_];    // w_proj split lo
__device__ __half g_aa [(size_t)M_ * C_];    // attention out, single fp16

// ---------------------------------------------------------------------------
// helpers
// ---------------------------------------------------------------------------
static __device__ __forceinline__ uint32_t smem_u32(const void* p) {
    uint32_t a;
    asm("{ .reg .u64 t; cvta.to.shared.u64 t, %1; cvt.u32.u64 %0, t; }"
        : "=r"(a) : "l"(p));
    return a;
}

#define CP16(dst, src) \
    asm volatile("cp.async.cg.shared.global [%0], [%1], 16;" \
                 :: "r"(dst), "l"(src))
#define CP_COMMIT() asm volatile("cp.async.commit_group;" ::: "memory")
#define CP_WAIT2()  asm volatile("cp.async.wait_group 2;"  ::: "memory")

#define LDSM_X4(r, addr) \
    asm volatile("ldmatrix.sync.aligned.m8n8.x4.shared.b16 {%0,%1,%2,%3}, [%4];" \
                 : "=r"((r)[0]), "=r"((r)[1]), "=r"((r)[2]), "=r"((r)[3]) \
                 : "r"(addr))

#define MMA_F16(d, a, b0, b1) \
    asm volatile("mma.sync.aligned.m16n8k16.row.col.f32.f16.f16.f32 " \
                 "{%0,%1,%2,%3}, {%4,%5,%6,%7}, {%8,%9}, {%0,%1,%2,%3};" \
                 : "+f"((d)[0]), "+f"((d)[1]), "+f"((d)[2]), "+f"((d)[3]) \
                 : "r"((a)[0]), "r"((a)[1]), "r"((a)[2]), "r"((a)[3]), \
                   "r"(b0), "r"(b1))

// smem tile: 128 rows x 64 bytes (32 fp16/row), XOR swizzle (conflict-free
// ldmatrix). 4 stages x 3 tiles (A, Bhi, Blo) x 8KB = 96KB.
static __device__ __forceinline__ uint32_t sw_off(int row, int c) {
    const int s = (row & 3) ^ ((row >> 2) & 3);
    return (uint32_t)(row * 64 + ((c ^ s) << 4));
}
#define TILE_ST(s, w) ((s) * 24576 + (w) * 8192)
#define GEMM_SMEM 98304
#define GEMM_GRID 592

// ---------------------------------------------------------------------------
// split kernels
// ---------------------------------------------------------------------------
__global__ void split_x_pe_f16(const float* __restrict__ x,
                               const float* __restrict__ pe,
                               __half* __restrict__ a)
{
    const size_t i4 = (size_t)blockIdx.x * blockDim.x + threadIdx.x;
    const size_t e  = i4 * 4;
    if (e >= (size_t)M_ * C_) return;
    const int row = (int)(e / C_);
    const int col = (int)(e % C_);
    const int tok = row % NTOK;

    float4 v = *reinterpret_cast<const float4*>(x + e);
    if (tok >= 4) {
        const float4 p = *reinterpret_cast<const float4*>(
            pe + (size_t)(tok + 28) * C_ + col);
        v.x += p.x; v.y += p.y; v.z += p.z; v.w += p.w;
    }
    __half2* ap = reinterpret_cast<__half2*>(a + e);
    ap[0] = __half2(__float2half_rn(v.x), __float2half_rn(v.y));
    ap[1] = __half2(__float2half_rn(v.z), __float2half_rn(v.w));
}

__global__ void split_w_f16(const float* __restrict__ w,
                            __half* __restrict__ hi,
                            __half* __restrict__ lo,
                            size_t n_elem)
{
    const size_t i4 = (size_t)blockIdx.x * blockDim.x + threadIdx.x;
    const size_t e  = i4 * 4;
    if (e >= n_elem) return;
    const float4 v = *reinterpret_cast<const float4*>(w + e);
    __half h0 = __float2half_rn(v.x), l0 = __float2half_rn(v.x - __half2float(h0));
    __half h1 = __float2half_rn(v.y), l1 = __float2half_rn(v.y - __half2float(h1));
    __half h2 = __float2half_rn(v.z), l2 = __float2half_rn(v.z - __half2float(h2));
    __half h3 = __float2half_rn(v.w), l3 = __float2half_rn(v.w - __half2float(h3));
    __half2* hp = reinterpret_cast<__half2*>(hi + e);
    __half2* lp = reinterpret_cast<__half2*>(lo + e);
    hp[0] = __half2(h0, h1); hp[1] = __half2(h2, h3);
    lp[0] = __half2(l0, l1); lp[1] = __half2(l2, l3);
}

// ---------------------------------------------------------------------------
// Persistent GEMM: C = A·W^T + bias, D = A*Bhi + A*Blo (fp16 mma, fp32 acc).
// A = fp16 activations (uncorrected ~2^-12), W split into fp16 hi+lo.
// CTA 128x128, 8 warps (2m x 4n), warp tile 64x32, K-chunk 32, 4-stage
// cp.async ring running continuously across tiles (persistent grid-stride),
// half-chunk fragment double-buffer, term-major MMA.
// ---------------------------------------------------------------------------
__global__ __launch_bounds__(256)
void gemm_f16x2_kernel(const __half* __restrict__ A,
                       const __half* __restrict__ Bhi,
                       const __half* __restrict__ Blo,
                       const float* __restrict__ bias,
                       float* __restrict__ Cout,
                       int N, int K, int NT, int TT)
{
    extern __shared__ char smem[];
    const uint32_t sb = smem_u32(smem);

    const int tid  = threadIdx.x;
    const int wid  = tid >> 5;
    const int lane = tid & 31;
    const int wm   = wid & 1;    // 0..1
    const int wn   = wid >> 1;   // 0..3

    // ---- cp.async geometry: 2 x 16B per thread per tile ----
    const int r0 = tid >> 2,         c0 = tid & 3;
    const int r1 = (tid + 256) >> 2, c1 = (tid + 256) & 3;
    const uint32_t so0 = sw_off(r0, c0);
    const uint32_t so1 = sw_off(r1, c1);

#define TILE_OFFSETS(lt_, a0_, a1_, b0_, b1_)                         \
    do {                                                              \
        const int cN_ = (lt_) % NT, cM_ = (lt_) / NT;                 \
        a0_ = (size_t)(cM_ * 128 + r0) * K + c0 * 8;                  \
        a1_ = (size_t)(cM_ * 128 + r1) * K + c1 * 8;                  \
        b0_ = (size_t)(cN_ * 128 + r0) * K + c0 * 8;                  \
        b1_ = (size_t)(cN_ * 128 + r1) * K + c1 * 8;                  \
    } while (0)

#define LOAD_STAGE(s, a0_, a1_, b0_, b1_, k0)                         \
    do {                                                              \
        CP16(sb + TILE_ST(s, 0) + so0, A   + (a0_) + (k0));           \
        CP16(sb + TILE_ST(s, 0) + so1, A   + (a1_) + (k0));           \
        CP16(sb + TILE_ST(s, 1) + so0, Bhi + (b0_) + (k0));           \
        CP16(sb + TILE_ST(s, 1) + so1, Bhi + (b1_) + (k0));           \
        CP16(sb + TILE_ST(s, 2) + so0, Blo + (b0_) + (k0));           \
        CP16(sb + TILE_ST(s, 2) + so1, Blo + (b1_) + (k0));           \
    } while (0)

    // per-warp ldmatrix base offsets
    const int arow = wm * 64 + (lane & 15);   // + mf*16
    const int brow = wn * 32 + (lane & 15);   // + bf*16
    const int chi  = lane >> 4;               // 16B column sub-chunk

#define FRAG_LOAD(Aa_, Bh_, Bl_, st, t)                                      \
    do {                                                                      \
        _Pragma("unroll")                                                     \
        for (int mf = 0; mf < 4; mf++) {                                      \
            const uint32_t ao = sw_off(arow + mf * 16, 2 * (t) + chi);        \
            LDSM_X4(Aa_[mf], sb + TILE_ST(st, 0) + ao);                       \
        }                                                                     \
        _Pragma("unroll")                                                     \
        for (int bf = 0; bf < 2; bf++) {                                      \
            const uint32_t bo = sw_off(brow + bf * 16, 2 * (t) + chi);        \
            LDSM_X4(Bh_[bf], sb + TILE_ST(st, 1) + bo);                       \
            LDSM_X4(Bl_[bf], sb + TILE_ST(st, 2) + bo);                       \
        }                                                                     \
    } while (0)

// term-major: 2 passes of 16 independent-accumulator MMAs each
#define MMA_ALL(Aa_, Bh_, Bl_)                                               \
    do {                                                                      \
        _Pragma("unroll")                                                     \
        for (int mf = 0; mf < 4; mf++) {                                      \
            _Pragma("unroll")                                                 \
            for (int nf = 0; nf < 4; nf++) {                                  \
                const int g = nf >> 1, h = nf & 1;                            \
                MMA_F16(acc[mf][nf], Aa_[mf], Bh_[g][h], Bh_[g][h + 2]);      \
            }                                                                 \
        }                                                                     \
        _Pragma("unroll")                                                     \
        for (int mf = 0; mf < 4; mf++) {                                      \
            _Pragma("unroll")                                                 \
            for (int nf = 0; nf < 4; nf++) {                                  \
                const int g = nf >> 1, h = nf & 1;                            \
                MMA_F16(acc[mf][nf], Aa_[mf], Bl_[g][h], Bl_[g][h + 2]);      \
            }                                                                 \
        }                                                                     \
    } while (0)

    float acc[4][4][4];
#pragma unroll
    for (int i = 0; i < 4; i++)
#pragma unroll
        for (int j = 0; j < 4; j++)
#pragma unroll
            for (int r = 0; r < 4; r++) acc[i][j][r] = 0.0f;

    const int NC = K >> 5;   // 24 (divisible by 4)

    uint32_t Aa0[4][4], Bh0[2][4], Bl0[2][4];
    uint32_t Aa1[4][4], Bh1[2][4], Bl1[2][4];

    int lt = blockIdx.x;
    if (lt >= TT) return;

    size_t a0, a1, b0, b1;
    TILE_OFFSETS(lt, a0, a1, b0, b1);

    // ---- prologue: 3 stages in flight, first half-chunk fragments loaded ----
    LOAD_STAGE(0, a0, a1, b0, b1, 0);   CP_COMMIT();
    LOAD_STAGE(1, a0, a1, b0, b1, 32);  CP_COMMIT();
    LOAD_STAGE(2, a0, a1, b0, b1, 64);  CP_COMMIT();
    CP_WAIT2();
    __syncthreads();
    FRAG_LOAD(Aa0, Bh0, Bl0, 0, 0);

    for (;;) {
        const int  ltn       = lt + (int)gridDim.x;
        const bool have_next = ltn < TT;
        size_t na0 = 0, na1 = 0, nb0 = 0, nb1 = 0;
        if (have_next) TILE_OFFSETS(ltn, na0, na1, nb0, nb1);

        for (int kc = 0; kc < NC; kc++) {
            const int cur = kc & 3;

            // prefetch second half of this chunk, then compute first half
            FRAG_LOAD(Aa1, Bh1, Bl1, cur, 1);
            MMA_ALL(Aa0, Bh0, Bl0);

            // refill slot freed last iteration; cross tile boundary if needed
            const int rc = kc + 3;
            if (rc < NC) {
                LOAD_STAGE(rc & 3, a0, a1, b0, b1, rc * 32);
            } else if (have_next) {
                LOAD_STAGE(rc & 3, na0, na1, nb0, nb1, (rc - NC) * 32);
            }
            CP_COMMIT();

            if (kc + 1 < NC) {
                CP_WAIT2();
                __syncthreads();
                FRAG_LOAD(Aa0, Bh0, Bl0, (kc + 1) & 3, 0);
            }
            MMA_ALL(Aa1, Bh1, Bl1);
        }

        // ---- epilogue for tile lt: bias + fp32 store (overlaps next loads) --
        {
            const int cN = lt % NT, cM = lt / NT;
#pragma unroll
            for (int mf = 0; mf < 4; mf++) {
                const int row = cM * 128 + wm * 64 + mf * 16 + (lane >> 2);
#pragma unroll
                for (int nf = 0; nf < 4; nf++) {
                    const int col = cN * 128 + wn * 32 + nf * 8 + (lane & 3) * 2;
                    const float2 bb = *reinterpret_cast<const float2*>(bias + col);
                    float2 o0, o1;
                    o0.x = acc[mf][nf][0] + bb.x;  o0.y = acc[mf][nf][1] + bb.y;
                    o1.x = acc[mf][nf][2] + bb.x;  o1.y = acc[mf][nf][3] + bb.y;
                    *reinterpret_cast<float2*>(Cout + (size_t)row * N + col) = o0;
                    *reinterpret_cast<float2*>(Cout + (size_t)(row + 8) * N + col) = o1;
                }
            }
        }
#pragma unroll
        for (int i = 0; i < 4; i++)
#pragma unroll
            for (int j = 0; j < 4; j++)
#pragma unroll
                for (int r = 0; r < 4; r++) acc[i][j][r] = 0.0f;

        if (!have_next) break;
        lt = ltn;
        a0 = na0; a1 = na1; b0 = nb0; b1 = nb1;

        // chunk 0 of the new tile (slot 0, loaded 3 refills ago)
        CP_WAIT2();
        __syncthreads();
        FRAG_LOAD(Aa0, Bh0, Bl0, 0, 0);
    }
#undef TILE_OFFSETS
#undef LOAD_STAGE
#undef FRAG_LOAD
#undef MMA_ALL
}

// ---------------------------------------------------------------------------
// Attention: one CTA per (b, h); 4 q-rows per warp per iteration so the
// sk/sv smem loads amortize 4x. Writes single fp16 output for the proj GEMM.
// ---------------------------------------------------------------------------
__global__ __launch_bounds__(256)
void attention_kernel(const float* __restrict__ qkv,
                      const float* __restrict__ mask,
                      __half* __restrict__ oa)
{
    __shared__ float sk[NTOK][HD + 1];
    __shared__ float sv[NTOK][HD + 1];
    __shared__ float sq[8][4][HD];
    __shared__ float sp[8][4][NTOK];

    const int bh = blockIdx.x;
    const int b  = bh / H_;
    const int h  = bh % H_;
    const int tid  = threadIdx.x;
    const int warp = tid >> 5;
    const int lane = tid & 31;

    const size_t base = (size_t)b * NTOK * K3C + (size_t)h * HD;
    for (int idx = tid; idx < NTOK * HD; idx += 256) {
        const int j = idx / HD, d = idx % HD;
        sk[j][d] = qkv[base + (size_t)j * K3C + C_ + d];
        sv[j][d] = qkv[base + (size_t)j * K3C + 2 * C_ + d];
    }
    __syncthreads();

    const float scale = 0.125f;
    const float* mrow_base = mask + (size_t)b * NTOK * NTOK;
    const int j0 = lane;
    const int j1 = lane + 32;
    const int j2 = (lane < 4) ? lane + 64 : 67;   // clamped; masked below

    // 17 groups of 4 rows
    for (int g = warp; g < 17; g += 8) {
        const int row0 = g * 4;

#pragma unroll
        for (int r = 0; r < 4; r++) {
            sq[warp][r][lane]      = qkv[base + (size_t)(row0 + r) * K3C + lane]      * scale;
            sq[warp][r][lane + 32] = qkv[base + (size_t)(row0 + r) * K3C + lane + 32] * scale;
        }
        __syncwarp();

        float s[4][3];
#pragma unroll
        for (int r = 0; r < 4; r++)
            s[r][0] = s[r][1] = s[r][2] = 0.0f;

#pragma unroll
        for (int d = 0; d < HD; d++) {
            const float k0 = sk[j0][d];
            const float k1 = sk[j1][d];
            const float k2 = sk[j2][d];
#pragma unroll
            for (int r = 0; r < 4; r++) {
                const float q = sq[warp][r][d];
                s[r][0] = fmaf(q, k0, s[r][0]);
                s[r][1] = fmaf(q, k1, s[r][1]);
                s[r][2] = fmaf(q, k2, s[r][2]);
            }
        }

#pragma unroll
        for (int r = 0; r < 4; r++) {
            const float* mrow = mrow_base + (size_t)(row0 + r) * NTOK;
            s[r][0] += mrow[j0];
            s[r][1] += mrow[j1];
            s[r][2] = (lane < 4) ? (s[r][2] + mrow[j2]) : -CUDART_INF_F;
        }

#pragma unroll
        for (int r = 0; r < 4; r++) {
            float mx = fmaxf(fmaxf(s[r][0], s[r][1]), s[r][2]);
#pragma unroll
            for (int off = 16; off > 0; off >>= 1)
                mx = fmaxf(mx, __shfl_xor_sync(0xffffffffu, mx, off));

            const float e0 = __expf(s[r][0] - mx);
            const float e1 = __expf(s[r][1] - mx);
            const float e2 = (lane < 4) ? __expf(s[r][2] - mx) : 0.0f;
            float sum = e0 + e1 + e2;
#pragma unroll
            for (int off = 16; off > 0; off >>= 1)
                sum += __shfl_xor_sync(0xffffffffu, sum, off);
            const float inv = 1.0f / sum;

            sp[warp][r][j0] = e0 * inv;
            sp[warp][r][j1] = e1 * inv;
            if (lane < 4) sp[warp][r][j2] = e2 * inv;
        }
        __syncwarp();

        float o[4][2];
#pragma unroll
        for (int r = 0; r < 4; r++) o[r][0] = o[r][1] = 0.0f;

#pragma unroll
        for (int j = 0; j < NTOK; j++) {
            const float v0 = sv[j][lane];
            const float v1 = sv[j][lane + 32];
#pragma unroll
            for (int r = 0; r < 4; r++) {
                const float p = sp[warp][r][j];
                o[r][0] = fmaf(p, v0, o[r][0]);
                o[r][1] = fmaf(p, v1, o[r][1]);
            }
        }

#pragma unroll
        for (int r = 0; r < 4; r++) {
            const size_t obase = ((size_t)b * NTOK + row0 + r) * C_ + (size_t)h * HD;
            oa[obase + lane]      = __float2half_rn(o[r][0]);
            oa[obase + lane + 32] = __float2half_rn(o[r][1]);
        }
        __syncwarp();
    }
}

// ---------------------------------------------------------------------------
extern "C" void kernel_launch(void* const* d_in, const int* in_sizes, int n_in,
                              void* d_out, int out_size)
{
    const float* x      = (const float*)d_in[0];
    const float* pe     = (const float*)d_in[1];
    const float* mask   = (const float*)d_in[2];
    const float* w_qkv  = (const float*)d_in[3];
    const float* b_qkv  = (const float*)d_in[4];
    const float* w_proj = (const float*)d_in[5];
    const float* b_proj = (const float*)d_in[6];
    float* out = (float*)d_out;

    float* qkv_buf; cudaGetSymbolAddress((void**)&qkv_buf, g_qkv);
    __half *xa, *whi, *wlo, *phi, *plo, *aa;
    cudaGetSymbolAddress((void**)&xa,  g_xa);
    cudaGetSymbolAddress((void**)&whi, g_whi);
    cudaGetSymbolAddress((void**)&wlo, g_wlo);
    cudaGetSymbolAddress((void**)&phi, g_phi);
    cudaGetSymbolAddress((void**)&plo, g_plo);
    cudaGetSymbolAddress((void**)&aa,  g_aa);

    cudaFuncSetAttribute(gemm_f16x2_kernel,
                         cudaFuncAttributeMaxDynamicSharedMemorySize, GEMM_SMEM);

    // 0) precompute fp16 activations + split weights
    {
        const size_t nx = (size_t)M_ * C_ / 4;
        split_x_pe_f16<<<(unsigned)((nx + 255) / 256), 256>>>(x, pe, xa);
        const size_t nw = (size_t)K3C * C_;
        split_w_f16<<<(unsigned)((nw / 4 + 255) / 256), 256>>>(w_qkv, whi, wlo, nw);
        const size_t np = (size_t)C_ * C_;
        split_w_f16<<<(unsigned)((np / 4 + 255) / 256), 256>>>(w_proj, phi, plo, np);
    }

    // 1) QKV projection: (M x 768) @ (768 x 2304)^T + bias -> g_qkv (fp32)
    {
        const int NT = K3C / 128;           // 18
        const int TT = (M_ / 128) * NT;     // 9792
        gemm_f16x2_kernel<<<GEMM_GRID, 256, GEMM_SMEM>>>(
            xa, whi, wlo, b_qkv, qkv_buf, K3C, C_, NT, TT);
    }

    // 2) Attention -> fp16 output
    attention_kernel<<<B_ * H_, 256>>>(qkv_buf, mask, aa);

    // 3) Output projection -> d_out
    {
        const int NT = C_ / 128;            // 6
        const int TT = (M_ / 128) * NT;     // 4080
        gemm_f16x2_kernel<<<GEMM_GRID, 256, GEMM_SMEM>>>(
            aa, phi, plo, b_proj, out, C_, C_, NT, TT);
    }
}

// round 13
// speedup vs baseline: 2.0177x; 1.0879x over previous
#include <cuda_runtime.h>
#include <cuda_fp16.h>
#include <math_constants.h>
#include <cstdint>

// Problem constants
#define B_   1024
#define NTOK 68
#define C_   768
#define H_   12
#define HD   64
#define M_   (B_ * NTOK)        // 69632
#define K3C  (3 * C_)           // 2304

// Scratch (__device__ globals; allocation-free rule)
__device__ float  g_qkv[(size_t)M_ * K3C];   // QKV output fp32
__device__ __half g_xa [(size_t)M_ * C_];    // x+pe, single fp16
__device__ __half g_whi[(size_t)K3C * C_];   // w_qkv split hi
__device__ __half g_wlo[(size_t)K3C * C_];   // w_qkv split lo
__device__ __half g_phi[(size_t)C_ * C_];    // w_proj split hi
__device__ __half g_plo[(size_t)C_ * C_];    // w_proj split lo
__device__ __half g_aa [(size_t)M_ * C_];    // attention out, single fp16

// ---------------------------------------------------------------------------
// helpers
// ---------------------------------------------------------------------------
static __device__ __forceinline__ uint32_t smem_u32(const void* p) {
    uint32_t a;
    asm("{ .reg .u64 t; cvta.to.shared.u64 t, %1; cvt.u32.u64 %0, t; }"
        : "=r"(a) : "l"(p));
    return a;
}

#define CP16(dst, src) \
    asm volatile("cp.async.cg.shared.global [%0], [%1], 16;" \
                 :: "r"(dst), "l"(src))
#define CP_COMMIT() asm volatile("cp.async.commit_group;" ::: "memory")
#define CP_WAIT2()  asm volatile("cp.async.wait_group 2;"  ::: "memory")

#define LDSM_X4(r, addr) \
    asm volatile("ldmatrix.sync.aligned.m8n8.x4.shared.b16 {%0,%1,%2,%3}, [%4];" \
                 : "=r"((r)[0]), "=r"((r)[1]), "=r"((r)[2]), "=r"((r)[3]) \
                 : "r"(addr))

#define MMA_F16(d, a, b0, b1) \
    asm volatile("mma.sync.aligned.m16n8k16.row.col.f32.f16.f16.f32 " \
                 "{%0,%1,%2,%3}, {%4,%5,%6,%7}, {%8,%9}, {%0,%1,%2,%3};" \
                 : "+f"((d)[0]), "+f"((d)[1]), "+f"((d)[2]), "+f"((d)[3]) \
                 : "r"((a)[0]), "r"((a)[1]), "r"((a)[2]), "r"((a)[3]), \
                   "r"(b0), "r"(b1))

// smem tile: 128 rows x 128 bytes (64 fp16 = one K-chunk of 64), canonical
// SW128 swizzle (16B chunk c in row r lives at c ^ (r & 7)) -> conflict-free
// ldmatrix + cp.async. 4 stages x 3 tiles (A, Bhi, Blo) x 16KB = 192KB.
static __device__ __forceinline__ uint32_t swf(int row, int c16) {
    return (uint32_t)(row * 128 + (((c16 ^ row) & 7) << 4));
}
#define TILE_ST(s, w) ((s) * 49152 + (w) * 16384)
#define GEMM_SMEM 196608
#define GEMM_GRID 592

// ---------------------------------------------------------------------------
// split kernels
// ---------------------------------------------------------------------------
__global__ void split_x_pe_f16(const float* __restrict__ x,
                               const float* __restrict__ pe,
                               __half* __restrict__ a)
{
    const size_t i4 = (size_t)blockIdx.x * blockDim.x + threadIdx.x;
    const size_t e  = i4 * 4;
    if (e >= (size_t)M_ * C_) return;
    const int row = (int)(e / C_);
    const int col = (int)(e % C_);
    const int tok = row % NTOK;

    float4 v = *reinterpret_cast<const float4*>(x + e);
    if (tok >= 4) {
        const float4 p = *reinterpret_cast<const float4*>(
            pe + (size_t)(tok + 28) * C_ + col);
        v.x += p.x; v.y += p.y; v.z += p.z; v.w += p.w;
    }
    __half2* ap = reinterpret_cast<__half2*>(a + e);
    ap[0] = __half2(__float2half_rn(v.x), __float2half_rn(v.y));
    ap[1] = __half2(__float2half_rn(v.z), __float2half_rn(v.w));
}

__global__ void split_w_f16(const float* __restrict__ w,
                            __half* __restrict__ hi,
                            __half* __restrict__ lo,
                            size_t n_elem)
{
    const size_t i4 = (size_t)blockIdx.x * blockDim.x + threadIdx.x;
    const size_t e  = i4 * 4;
    if (e >= n_elem) return;
    const float4 v = *reinterpret_cast<const float4*>(w + e);
    __half h0 = __float2half_rn(v.x), l0 = __float2half_rn(v.x - __half2float(h0));
    __half h1 = __float2half_rn(v.y), l1 = __float2half_rn(v.y - __half2float(h1));
    __half h2 = __float2half_rn(v.z), l2 = __float2half_rn(v.z - __half2float(h2));
    __half h3 = __float2half_rn(v.w), l3 = __float2half_rn(v.w - __half2float(h3));
    __half2* hp = reinterpret_cast<__half2*>(hi + e);
    __half2* lp = reinterpret_cast<__half2*>(lo + e);
    hp[0] = __half2(h0, h1); hp[1] = __half2(h2, h3);
    lp[0] = __half2(l0, l1); lp[1] = __half2(l2, l3);
}

// ---------------------------------------------------------------------------
// Persistent GEMM: C = A·W^T + bias, D = A*Bhi + A*Blo (fp16 mma, fp32 acc).
// CTA 128x128, 8 warps (2m x 4n), warp tile 64x32, K-chunk 64 (4 quarter-K
// fragment rounds per single barrier), 4-stage cp.async ring running
// continuously across persistent grid-stride tiles, term-major MMA.
// NC = K/64 = 12, divisible by 4 -> ring phase continuous across tiles.
// ---------------------------------------------------------------------------
__global__ __launch_bounds__(256)
void gemm_f16x2_kernel(const __half* __restrict__ A,
                       const __half* __restrict__ Bhi,
                       const __half* __restrict__ Blo,
                       const float* __restrict__ bias,
                       float* __restrict__ Cout,
                       int N, int K, int NT, int TT)
{
    extern __shared__ char smem[];
    const uint32_t sb = smem_u32(smem);

    const int tid  = threadIdx.x;
    const int wid  = tid >> 5;
    const int lane = tid & 31;
    const int wm   = wid & 1;    // 0..1
    const int wn   = wid >> 1;   // 0..3

    // ---- cp.async geometry: 4 x 16B per thread per tile ----
    // base slot: row0 = tid>>3 (0..31), c16 = tid&7; i-th slot: row0 + 32*i.
    // (32*i doesn't change row&7, so swizzle offset just adds 4096*i.)
    const int r0  = tid >> 3, c16 = tid & 7;
    const uint32_t so = swf(r0, c16);

#define TILE_OFFSETS(lt_, ao_, bo_)                                   \
    do {                                                              \
        const int cN_ = (lt_) % NT, cM_ = (lt_) / NT;                 \
        ao_ = (size_t)(cM_ * 128 + r0) * K + c16 * 8;                 \
        bo_ = (size_t)(cN_ * 128 + r0) * K + c16 * 8;                 \
    } while (0)

#define LOAD_STAGE(s, ao_, bo_, k0)                                          \
    do {                                                                      \
        _Pragma("unroll")                                                     \
        for (int i = 0; i < 4; i++) {                                         \
            const uint32_t d = so + 4096u * i;                                \
            const size_t   g = (size_t)(32 * i) * K + (k0);                   \
            CP16(sb + TILE_ST(s, 0) + d, A   + (ao_) + g);                    \
            CP16(sb + TILE_ST(s, 1) + d, Bhi + (bo_) + g);                    \
            CP16(sb + TILE_ST(s, 2) + d, Blo + (bo_) + g);                    \
        }                                                                     \
    } while (0)

    // per-warp ldmatrix base rows
    const int arow = wm * 64 + (lane & 15);   // + mf*16
    const int brow = wn * 32 + (lane & 15);   // + bf*16
    const int chi  = lane >> 4;               // 16B sub-chunk within quarter

#define FRAG_LOAD(Aa_, Bh_, Bl_, st, t)                                      \
    do {                                                                      \
        _Pragma("unroll")                                                     \
        for (int mf = 0; mf < 4; mf++) {                                      \
            const uint32_t ao = swf(arow + mf * 16, 2 * (t) + chi);           \
            LDSM_X4(Aa_[mf], sb + TILE_ST(st, 0) + ao);                       \
        }                                                                     \
        _Pragma("unroll")                                                     \
        for (int bf = 0; bf < 2; bf++) {                                      \
            const uint32_t bo = swf(brow + bf * 16, 2 * (t) + chi);           \
            LDSM_X4(Bh_[bf], sb + TILE_ST(st, 1) + bo);                       \
            LDSM_X4(Bl_[bf], sb + TILE_ST(st, 2) + bo);                       \
        }                                                                     \
    } while (0)

// term-major: 2 passes of 16 independent-accumulator MMAs each
#define MMA_ALL(Aa_, Bh_, Bl_)                                               \
    do {                                                                      \
        _Pragma("unroll")                                                     \
        for (int mf = 0; mf < 4; mf++) {                                      \
            _Pragma("unroll")                                                 \
            for (int nf = 0; nf < 4; nf++) {                                  \
                const int g = nf >> 1, h = nf & 1;                            \
                MMA_F16(acc[mf][nf], Aa_[mf], Bh_[g][h], Bh_[g][h + 2]);      \
            }                                                                 \
        }                                                                     \
        _Pragma("unroll")                                                     \
        for (int mf = 0; mf < 4; mf++) {                                      \
            _Pragma("unroll")                                                 \
            for (int nf = 0; nf < 4; nf++) {                                  \
                const int g = nf >> 1, h = nf & 1;                            \
                MMA_F16(acc[mf][nf], Aa_[mf], Bl_[g][h], Bl_[g][h + 2]);      \
            }                                                                 \
        }                                                                     \
    } while (0)

    float acc[4][4][4];
#pragma unroll
    for (int i = 0; i < 4; i++)
#pragma unroll
        for (int j = 0; j < 4; j++)
#pragma unroll
            for (int r = 0; r < 4; r++) acc[i][j][r] = 0.0f;

    const int NC = K >> 6;   // 12 (divisible by 4)

    uint32_t Aa0[4][4], Bh0[2][4], Bl0[2][4];
    uint32_t Aa1[4][4], Bh1[2][4], Bl1[2][4];

    int lt = blockIdx.x;
    if (lt >= TT) return;

    size_t ao, bo;
    TILE_OFFSETS(lt, ao, bo);

    // ---- prologue: 3 stages in flight, quarter-0 fragments loaded ----
    LOAD_STAGE(0, ao, bo, 0);    CP_COMMIT();
    LOAD_STAGE(1, ao, bo, 64);   CP_COMMIT();
    LOAD_STAGE(2, ao, bo, 128);  CP_COMMIT();
    CP_WAIT2();
    __syncthreads();
    FRAG_LOAD(Aa0, Bh0, Bl0, 0, 0);

    for (;;) {
        const int  ltn       = lt + (int)gridDim.x;
        const bool have_next = ltn < TT;
        size_t nao = 0, nbo = 0;
        if (have_next) TILE_OFFSETS(ltn, nao, nbo);

        for (int kc = 0; kc < NC; kc++) {
            const int cur = kc & 3;

            // quarter 1 prefetch, quarter 0 compute
            FRAG_LOAD(Aa1, Bh1, Bl1, cur, 1);
            MMA_ALL(Aa0, Bh0, Bl0);

            // refill slot freed last iteration (one group per 64-K chunk)
            const int rc = kc + 3;
            if (rc < NC) {
                LOAD_STAGE(rc & 3, ao, bo, rc * 64);
            } else if (have_next) {
                LOAD_STAGE(rc & 3, nao, nbo, (rc - NC) * 64);
            }
            CP_COMMIT();

            // quarters 2 and 3
            FRAG_LOAD(Aa0, Bh0, Bl0, cur, 2);
            MMA_ALL(Aa1, Bh1, Bl1);
            FRAG_LOAD(Aa1, Bh1, Bl1, cur, 3);
            MMA_ALL(Aa0, Bh0, Bl0);

            if (kc + 1 < NC) {
                CP_WAIT2();
                __syncthreads();
                FRAG_LOAD(Aa0, Bh0, Bl0, (kc + 1) & 3, 0);
            }
            MMA_ALL(Aa1, Bh1, Bl1);
        }

        // ---- epilogue for tile lt: bias + fp32 store (overlaps next loads) --
        {
            const int cN = lt % NT, cM = lt / NT;
#pragma unroll
            for (int mf = 0; mf < 4; mf++) {
                const int row = cM * 128 + wm * 64 + mf * 16 + (lane >> 2);
#pragma unroll
                for (int nf = 0; nf < 4; nf++) {
                    const int col = cN * 128 + wn * 32 + nf * 8 + (lane & 3) * 2;
                    const float2 bb = *reinterpret_cast<const float2*>(bias + col);
                    float2 o0, o1;
                    o0.x = acc[mf][nf][0] + bb.x;  o0.y = acc[mf][nf][1] + bb.y;
                    o1.x = acc[mf][nf][2] + bb.x;  o1.y = acc[mf][nf][3] + bb.y;
                    *reinterpret_cast<float2*>(Cout + (size_t)row * N + col) = o0;
                    *reinterpret_cast<float2*>(Cout + (size_t)(row + 8) * N + col) = o1;
                }
            }
        }
#pragma unroll
        for (int i = 0; i < 4; i++)
#pragma unroll
            for (int j = 0; j < 4; j++)
#pragma unroll
                for (int r = 0; r < 4; r++) acc[i][j][r] = 0.0f;

        if (!have_next) break;
        lt = ltn;
        ao = nao; bo = nbo;

        // chunk 0 of the new tile (slot 0, loaded by the rc==NC refill)
        CP_WAIT2();
        __syncthreads();
        FRAG_LOAD(Aa0, Bh0, Bl0, 0, 0);
    }
#undef TILE_OFFSETS
#undef LOAD_STAGE
#undef FRAG_LOAD
#undef MMA_ALL
}

// ---------------------------------------------------------------------------
// Attention: one CTA per (b, h); 4 q-rows per warp per iteration so the
// sk/sv smem loads amortize 4x. Writes single fp16 output for the proj GEMM.
// ---------------------------------------------------------------------------
__global__ __launch_bounds__(256)
void attention_kernel(const float* __restrict__ qkv,
                      const float* __restrict__ mask,
                      __half* __restrict__ oa)
{
    __shared__ float sk[NTOK][HD + 1];
    __shared__ float sv[NTOK][HD + 1];
    __shared__ float sq[8][4][HD];
    __shared__ float sp[8][4][NTOK];

    const int bh = blockIdx.x;
    const int b  = bh / H_;
    const int h  = bh % H_;
    const int tid  = threadIdx.x;
    const int warp = tid >> 5;
    const int lane = tid & 31;

    const size_t base = (size_t)b * NTOK * K3C + (size_t)h * HD;
    for (int idx = tid; idx < NTOK * HD; idx += 256) {
        const int j = idx / HD, d = idx % HD;
        sk[j][d] = qkv[base + (size_t)j * K3C + C_ + d];
        sv[j][d] = qkv[base + (size_t)j * K3C + 2 * C_ + d];
    }
    __syncthreads();

    const float scale = 0.125f;
    const float* mrow_base = mask + (size_t)b * NTOK * NTOK;
    const int j0 = lane;
    const int j1 = lane + 32;
    const int j2 = (lane < 4) ? lane + 64 : 67;   // clamped; masked below

    // 17 groups of 4 rows
    for (int g = warp; g < 17; g += 8) {
        const int row0 = g * 4;

#pragma unroll
        for (int r = 0; r < 4; r++) {
            sq[warp][r][lane]      = qkv[base + (size_t)(row0 + r) * K3C + lane]      * scale;
            sq[warp][r][lane + 32] = qkv[base + (size_t)(row0 + r) * K3C + lane + 32] * scale;
        }
        __syncwarp();

        float s[4][3];
#pragma unroll
        for (int r = 0; r < 4; r++)
            s[r][0] = s[r][1] = s[r][2] = 0.0f;

#pragma unroll
        for (int d = 0; d < HD; d++) {
            const float k0 = sk[j0][d];
            const float k1 = sk[j1][d];
            const float k2 = sk[j2][d];
#pragma unroll
            for (int r = 0; r < 4; r++) {
                const float q = sq[warp][r][d];
                s[r][0] = fmaf(q, k0, s[r][0]);
                s[r][1] = fmaf(q, k1, s[r][1]);
                s[r][2] = fmaf(q, k2, s[r][2]);
            }
        }

#pragma unroll
        for (int r = 0; r < 4; r++) {
            const float* mrow = mrow_base + (size_t)(row0 + r) * NTOK;
            s[r][0] += mrow[j0];
            s[r][1] += mrow[j1];
            s[r][2] = (lane < 4) ? (s[r][2] + mrow[j2]) : -CUDART_INF_F;
        }

#pragma unroll
        for (int r = 0; r < 4; r++) {
            float mx = fmaxf(fmaxf(s[r][0], s[r][1]), s[r][2]);
#pragma unroll
            for (int off = 16; off > 0; off >>= 1)
                mx = fmaxf(mx, __shfl_xor_sync(0xffffffffu, mx, off));

            const float e0 = __expf(s[r][0] - mx);
            const float e1 = __expf(s[r][1] - mx);
            const float e2 = (lane < 4) ? __expf(s[r][2] - mx) : 0.0f;
            float sum = e0 + e1 + e2;
#pragma unroll
            for (int off = 16; off > 0; off >>= 1)
                sum += __shfl_xor_sync(0xffffffffu, sum, off);
            const float inv = 1.0f / sum;

            sp[warp][r][j0] = e0 * inv;
            sp[warp][r][j1] = e1 * inv;
            if (lane < 4) sp[warp][r][j2] = e2 * inv;
        }
        __syncwarp();

        float o[4][2];
#pragma unroll
        for (int r = 0; r < 4; r++) o[r][0] = o[r][1] = 0.0f;

#pragma unroll
        for (int j = 0; j < NTOK; j++) {
            const float v0 = sv[j][lane];
            const float v1 = sv[j][lane + 32];
#pragma unroll
            for (int r = 0; r < 4; r++) {
                const float p = sp[warp][r][j];
                o[r][0] = fmaf(p, v0, o[r][0]);
                o[r][1] = fmaf(p, v1, o[r][1]);
            }
        }

#pragma unroll
        for (int r = 0; r < 4; r++) {
            const size_t obase = ((size_t)b * NTOK + row0 + r) * C_ + (size_t)h * HD;
            oa[obase + lane]      = __float2half_rn(o[r][0]);
            oa[obase + lane + 32] = __float2half_rn(o[r][1]);
        }
        __syncwarp();
    }
}

// ---------------------------------------------------------------------------
extern "C" void kernel_launch(void* const* d_in, const int* in_sizes, int n_in,
                              void* d_out, int out_size)
{
    const float* x      = (const float*)d_in[0];
    const float* pe     = (const float*)d_in[1];
    const float* mask   = (const float*)d_in[2];
    const float* w_qkv  = (const float*)d_in[3];
    const float* b_qkv  = (const float*)d_in[4];
    const float* w_proj = (const float*)d_in[5];
    const float* b_proj = (const float*)d_in[6];
    float* out = (float*)d_out;

    float* qkv_buf; cudaGetSymbolAddress((void**)&qkv_buf, g_qkv);
    __half *xa, *whi, *wlo, *phi, *plo, *aa;
    cudaGetSymbolAddress((void**)&xa,  g_xa);
    cudaGetSymbolAddress((void**)&whi, g_whi);
    cudaGetSymbolAddress((void**)&wlo, g_wlo);
    cudaGetSymbolAddress((void**)&phi, g_phi);
    cudaGetSymbolAddress((void**)&plo, g_plo);
    cudaGetSymbolAddress((void**)&aa,  g_aa);

    cudaFuncSetAttribute(gemm_f16x2_kernel,
                         cudaFuncAttributeMaxDynamicSharedMemorySize, GEMM_SMEM);

    // 0) precompute fp16 activations + split weights
    {
        const size_t nx = (size_t)M_ * C_ / 4;
        split_x_pe_f16<<<(unsigned)((nx + 255) / 256), 256>>>(x, pe, xa);
        const size_t nw = (size_t)K3C * C_;
        split_w_f16<<<(unsigned)((nw / 4 + 255) / 256), 256>>>(w_qkv, whi, wlo, nw);
        const size_t np = (size_t)C_ * C_;
        split_w_f16<<<(unsigned)((np / 4 + 255) / 256), 256>>>(w_proj, phi, plo, np);
    }

    // 1) QKV projection: (M x 768) @ (768 x 2304)^T + bias -> g_qkv (fp32)
    {
        const int NT = K3C / 128;           // 18
        const int TT = (M_ / 128) * NT;     // 9792
        gemm_f16x2_kernel<<<GEMM_GRID, 256, GEMM_SMEM>>>(
            xa, whi, wlo, b_qkv, qkv_buf, K3C, C_, NT, TT);
    }

    // 2) Attention -> fp16 output
    attention_kernel<<<B_ * H_, 256>>>(qkv_buf, mask, aa);

    // 3) Output projection -> d_out
    {
        const int NT = C_ / 128;            // 6
        const int TT = (M_ / 128) * NT;     // 4080
        gemm_f16x2_kernel<<<GEMM_GRID, 256, GEMM_SMEM>>>(
            aa, phi, plo, b_proj, out, C_, C_, NT, TT);
    }
}

// round 14
// speedup vs baseline: 2.0384x; 1.0103x over previous
#include <cuda_runtime.h>
#include <cuda_fp16.h>
#include <math_constants.h>
#include <cstdint>

// Problem constants
#define B_   1024
#define NTOK 68
#define C_   768
#define H_   12
#define HD   64
#define M_   (B_ * NTOK)        // 69632
#define K3C  (3 * C_)           // 2304

// Scratch (__device__ globals; allocation-free rule)
__device__ float  g_qkv[(size_t)M_ * K3C];   // QKV output fp32
__device__ __half g_xa [(size_t)M_ * C_];    // x+pe, single fp16
__device__ __half g_whi[(size_t)K3C * C_];   // w_qkv split hi
__device__ __half g_wlo[(size_t)K3C * C_];   // w_qkv split lo
__device__ __half g_phi[(size_t)C_ * C_];    // w_proj split hi
__device__ __half g_plo[(size_t)C_ * C_];    // w_proj split lo
__device__ __half g_aa [(size_t)M_ * C_];    // attention out, single fp16

// ---------------------------------------------------------------------------
// helpers
// ---------------------------------------------------------------------------
static __device__ __forceinline__ uint32_t smem_u32(const void* p) {
    uint32_t a;
    asm("{ .reg .u64 t; cvta.to.shared.u64 t, %1; cvt.u32.u64 %0, t; }"
        : "=r"(a) : "l"(p));
    return a;
}

#define CP16(dst, src) \
    asm volatile("cp.async.cg.shared.global [%0], [%1], 16;" \
                 :: "r"(dst), "l"(src))
#define CP_COMMIT() asm volatile("cp.async.commit_group;" ::: "memory")
#define CP_WAIT1()  asm volatile("cp.async.wait_group 1;"  ::: "memory")

#define LDSM_X4(r, addr) \
    asm volatile("ldmatrix.sync.aligned.m8n8.x4.shared.b16 {%0,%1,%2,%3}, [%4];" \
                 : "=r"((r)[0]), "=r"((r)[1]), "=r"((r)[2]), "=r"((r)[3]) \
                 : "r"(addr))

#define MMA_F16(d, a, b0, b1) \
    asm volatile("mma.sync.aligned.m16n8k16.row.col.f32.f16.f16.f32 " \
                 "{%0,%1,%2,%3}, {%4,%5,%6,%7}, {%8,%9}, {%0,%1,%2,%3};" \
                 : "+f"((d)[0]), "+f"((d)[1]), "+f"((d)[2]), "+f"((d)[3]) \
                 : "r"((a)[0]), "r"((a)[1]), "r"((a)[2]), "r"((a)[3]), \
                   "r"(b0), "r"(b1))

// smem tile: 128 rows x 128 bytes (64 fp16 = one K-chunk of 64), canonical
// SW128 swizzle (16B chunk c in row r lives at c ^ (r & 7)) -> conflict-free
// ldmatrix + cp.async. 2 stages x 3 tiles (A, Bhi, Blo) x 16KB = 96KB
// -> 2 CTAs per SM (192KB <= 228KB).
static __device__ __forceinline__ uint32_t swf(int row, int c16) {
    return (uint32_t)(row * 128 + (((c16 ^ row) & 7) << 4));
}
#define TILE_ST(s, w) ((s) * 49152 + (w) * 16384)
#define GEMM_SMEM 98304
#define GEMM_GRID 1184

// ---------------------------------------------------------------------------
// split kernels
// ---------------------------------------------------------------------------
__global__ void split_x_pe_f16(const float* __restrict__ x,
                               const float* __restrict__ pe,
                               __half* __restrict__ a)
{
    const size_t i4 = (size_t)blockIdx.x * blockDim.x + threadIdx.x;
    const size_t e  = i4 * 4;
    if (e >= (size_t)M_ * C_) return;
    const int row = (int)(e / C_);
    const int col = (int)(e % C_);
    const int tok = row % NTOK;

    float4 v = *reinterpret_cast<const float4*>(x + e);
    if (tok >= 4) {
        const float4 p = *reinterpret_cast<const float4*>(
            pe + (size_t)(tok + 28) * C_ + col);
        v.x += p.x; v.y += p.y; v.z += p.z; v.w += p.w;
    }
    __half2* ap = reinterpret_cast<__half2*>(a + e);
    ap[0] = __half2(__float2half_rn(v.x), __float2half_rn(v.y));
    ap[1] = __half2(__float2half_rn(v.z), __float2half_rn(v.w));
}

__global__ void split_w_f16(const float* __restrict__ w,
                            __half* __restrict__ hi,
                            __half* __restrict__ lo,
                            size_t n_elem)
{
    const size_t i4 = (size_t)blockIdx.x * blockDim.x + threadIdx.x;
    const size_t e  = i4 * 4;
    if (e >= n_elem) return;
    const float4 v = *reinterpret_cast<const float4*>(w + e);
    __half h0 = __float2half_rn(v.x), l0 = __float2half_rn(v.x - __half2float(h0));
    __half h1 = __float2half_rn(v.y), l1 = __float2half_rn(v.y - __half2float(h1));
    __half h2 = __float2half_rn(v.z), l2 = __float2half_rn(v.z - __half2float(h2));
    __half h3 = __float2half_rn(v.w), l3 = __float2half_rn(v.w - __half2float(h3));
    __half2* hp = reinterpret_cast<__half2*>(hi + e);
    __half2* lp = reinterpret_cast<__half2*>(lo + e);
    hp[0] = __half2(h0, h1); hp[1] = __half2(h2, h3);
    lp[0] = __half2(l0, l1); lp[1] = __half2(l2, l3);
}

// ---------------------------------------------------------------------------
// Persistent GEMM: C = A·W^T + bias, D = A*Bhi + A*Blo (fp16 mma, fp32 acc).
// CTA 128x128, 8 warps (2m x 4n), warp tile 64x32, K-chunk 64 (4 quarter-K
// fragment rounds), 2-stage cp.async ring, single fragment buffer, 2 CTAs/SM
// (cross-CTA arbitration hides the barrier-correlated LDSM phases),
// persistent grid-stride tiles with the ring running across boundaries.
// NC = K/64 = 12 (even -> slot phase continuous across tiles).
// ---------------------------------------------------------------------------
__global__ __launch_bounds__(256, 2)
void gemm_f16x2_kernel(const __half* __restrict__ A,
                       const __half* __restrict__ Bhi,
                       const __half* __restrict__ Blo,
                       const float* __restrict__ bias,
                       float* __restrict__ Cout,
                       int N, int K, int NT, int TT)
{
    extern __shared__ char smem[];
    const uint32_t sb = smem_u32(smem);

    const int tid  = threadIdx.x;
    const int wid  = tid >> 5;
    const int lane = tid & 31;
    const int wm   = wid & 1;    // 0..1
    const int wn   = wid >> 1;   // 0..3

    // ---- cp.async geometry: 4 x 16B per thread per tile ----
    const int r0  = tid >> 3, c16 = tid & 7;
    const uint32_t so = swf(r0, c16);

#define TILE_OFFSETS(lt_, ao_, bo_)                                   \
    do {                                                              \
        const int cN_ = (lt_) % NT, cM_ = (lt_) / NT;                 \
        ao_ = (size_t)(cM_ * 128 + r0) * K + c16 * 8;                 \
        bo_ = (size_t)(cN_ * 128 + r0) * K + c16 * 8;                 \
    } while (0)

#define LOAD_STAGE(s, ao_, bo_, k0)                                          \
    do {                                                                      \
        _Pragma("unroll")                                                     \
        for (int i = 0; i < 4; i++) {                                         \
            const uint32_t d = so + 4096u * i;                                \
            const size_t   g = (size_t)(32 * i) * K + (k0);                   \
            CP16(sb + TILE_ST(s, 0) + d, A   + (ao_) + g);                    \
            CP16(sb + TILE_ST(s, 1) + d, Bhi + (bo_) + g);                    \
            CP16(sb + TILE_ST(s, 2) + d, Blo + (bo_) + g);                    \
        }                                                                     \
    } while (0)

    // per-warp ldmatrix base rows
    const int arow = wm * 64 + (lane & 15);   // + mf*16
    const int brow = wn * 32 + (lane & 15);   // + bf*16
    const int chi  = lane >> 4;               // 16B sub-chunk within quarter

#define FRAG_LOAD(st, t)                                                     \
    do {                                                                      \
        _Pragma("unroll")                                                     \
        for (int mf = 0; mf < 4; mf++) {                                      \
            const uint32_t ao_ = swf(arow + mf * 16, 2 * (t) + chi);          \
            LDSM_X4(Aa[mf], sb + TILE_ST(st, 0) + ao_);                       \
        }                                                                     \
        _Pragma("unroll")                                                     \
        for (int bf = 0; bf < 2; bf++) {                                      \
            const uint32_t bo_ = swf(brow + bf * 16, 2 * (t) + chi);          \
            LDSM_X4(Bh[bf], sb + TILE_ST(st, 1) + bo_);                       \
            LDSM_X4(Bl[bf], sb + TILE_ST(st, 2) + bo_);                       \
        }                                                                     \
    } while (0)

// term-major: 2 passes of 16 independent-accumulator MMAs each
#define MMA_ALL()                                                            \
    do {                                                                      \
        _Pragma("unroll")                                                     \
        for (int mf = 0; mf < 4; mf++) {                                      \
            _Pragma("unroll")                                                 \
            for (int nf = 0; nf < 4; nf++) {                                  \
                const int g = nf >> 1, h = nf & 1;                            \
                MMA_F16(acc[mf][nf], Aa[mf], Bh[g][h], Bh[g][h + 2]);         \
            }                                                                 \
        }                                                                     \
        _Pragma("unroll")                                                     \
        for (int mf = 0; mf < 4; mf++) {                                      \
            _Pragma("unroll")                                                 \
            for (int nf = 0; nf < 4; nf++) {                                  \
                const int g = nf >> 1, h = nf & 1;                            \
                MMA_F16(acc[mf][nf], Aa[mf], Bl[g][h], Bl[g][h + 2]);         \
            }                                                                 \
        }                                                                     \
    } while (0)

    float acc[4][4][4];
#pragma unroll
    for (int i = 0; i < 4; i++)
#pragma unroll
        for (int j = 0; j < 4; j++)
#pragma unroll
            for (int r = 0; r < 4; r++) acc[i][j][r] = 0.0f;

    const int NC = K >> 6;   // 12 (even)

    uint32_t Aa[4][4], Bh[2][4], Bl[2][4];

    int lt = blockIdx.x;
    if (lt >= TT) return;

    size_t ao, bo;
    TILE_OFFSETS(lt, ao, bo);

    // ---- prologue: both stages in flight ----
    LOAD_STAGE(0, ao, bo, 0);    CP_COMMIT();
    LOAD_STAGE(1, ao, bo, 64);   CP_COMMIT();
    CP_WAIT1();
    __syncthreads();   // chunk 0 ready for all threads

    for (;;) {
        for (int kc = 0; kc < NC; kc++) {
            const int cur = kc & 1;

            // compute chunk kc: 4 quarter rounds from slot cur
            FRAG_LOAD(cur, 0); MMA_ALL();
            FRAG_LOAD(cur, 1); MMA_ALL();
            FRAG_LOAD(cur, 2); MMA_ALL();
            FRAG_LOAD(cur, 3); MMA_ALL();

            __syncthreads();   // all warps done reading slot cur

            // refill slot cur with chunk kc+2 (crossing tile boundary)
            const int rc = kc + 2;
            if (rc < NC) {
                LOAD_STAGE(cur, ao, bo, rc * 64);
            } else {
                const int ltn = lt + (int)gridDim.x;
                if (ltn < TT) {
                    size_t nao, nbo;
                    TILE_OFFSETS(ltn, nao, nbo);
                    LOAD_STAGE(cur, nao, nbo, (rc - NC) * 64);
                }
            }
            CP_COMMIT();

            CP_WAIT1();        // chunk kc+1 (issued 2 groups ago) complete
            __syncthreads();   // visible to all warps
        }

        // ---- epilogue for tile lt (next tile's chunk 0/1 loads in flight) --
        {
            const int cN = lt % NT, cM = lt / NT;
#pragma unroll
            for (int mf = 0; mf < 4; mf++) {
                const int row = cM * 128 + wm * 64 + mf * 16 + (lane >> 2);
#pragma unroll
                for (int nf = 0; nf < 4; nf++) {
                    const int col = cN * 128 + wn * 32 + nf * 8 + (lane & 3) * 2;
                    const float2 bb = *reinterpret_cast<const float2*>(bias + col);
                    float2 o0, o1;
                    o0.x = acc[mf][nf][0] + bb.x;  o0.y = acc[mf][nf][1] + bb.y;
                    o1.x = acc[mf][nf][2] + bb.x;  o1.y = acc[mf][nf][3] + bb.y;
                    *reinterpret_cast<float2*>(Cout + (size_t)row * N + col) = o0;
                    *reinterpret_cast<float2*>(Cout + (size_t)(row + 8) * N + col) = o1;
                }
            }
        }
#pragma unroll
        for (int i = 0; i < 4; i++)
#pragma unroll
            for (int j = 0; j < 4; j++)
#pragma unroll
                for (int r = 0; r < 4; r++) acc[i][j][r] = 0.0f;

        lt += (int)gridDim.x;
        if (lt >= TT) break;
        TILE_OFFSETS(lt, ao, bo);
        // slot 0 already holds new tile's chunk 0 (refilled at kc=NC-2),
        // slot 1 holds chunk 1 (refilled at kc=NC-1); both waited+synced.
    }
#undef TILE_OFFSETS
#undef LOAD_STAGE
#undef FRAG_LOAD
#undef MMA_ALL
}

// ---------------------------------------------------------------------------
// Attention: one CTA per (b, h); 4 q-rows per warp per iteration so the
// sk/sv smem loads amortize 4x. Writes single fp16 output for the proj GEMM.
// ---------------------------------------------------------------------------
__global__ __launch_bounds__(256)
void attention_kernel(const float* __restrict__ qkv,
                      const float* __restrict__ mask,
                      __half* __restrict__ oa)
{
    __shared__ float sk[NTOK][HD + 1];
    __shared__ float sv[NTOK][HD + 1];
    __shared__ float sq[8][4][HD];
    __shared__ float sp[8][4][NTOK];

    const int bh = blockIdx.x;
    const int b  = bh / H_;
    const int h  = bh % H_;
    const int tid  = threadIdx.x;
    const int warp = tid >> 5;
    const int lane = tid & 31;

    const size_t base = (size_t)b * NTOK * K3C + (size_t)h * HD;
    for (int idx = tid; idx < NTOK * HD; idx += 256) {
        const int j = idx / HD, d = idx % HD;
        sk[j][d] = qkv[base + (size_t)j * K3C + C_ + d];
        sv[j][d] = qkv[base + (size_t)j * K3C + 2 * C_ + d];
    }
    __syncthreads();

    const float scale = 0.125f;
    const float* mrow_base = mask + (size_t)b * NTOK * NTOK;
    const int j0 = lane;
    const int j1 = lane + 32;
    const int j2 = (lane < 4) ? lane + 64 : 67;   // clamped; masked below

    // 17 groups of 4 rows
    for (int g = warp; g < 17; g += 8) {
        const int row0 = g * 4;

#pragma unroll
        for (int r = 0; r < 4; r++) {
            sq[warp][r][lane]      = qkv[base + (size_t)(row0 + r) * K3C + lane]      * scale;
            sq[warp][r][lane + 32] = qkv[base + (size_t)(row0 + r) * K3C + lane + 32] * scale;
        }
        __syncwarp();

        float s[4][3];
#pragma unroll
        for (int r = 0; r < 4; r++)
            s[r][0] = s[r][1] = s[r][2] = 0.0f;

#pragma unroll
        for (int d = 0; d < HD; d++) {
            const float k0 = sk[j0][d];
            const float k1 = sk[j1][d];
            const float k2 = sk[j2][d];
#pragma unroll
            for (int r = 0; r < 4; r++) {
                const float q = sq[warp][r][d];
                s[r][0] = fmaf(q, k0, s[r][0]);
                s[r][1] = fmaf(q, k1, s[r][1]);
                s[r][2] = fmaf(q, k2, s[r][2]);
            }
        }

#pragma unroll
        for (int r = 0; r < 4; r++) {
            const float* mrow = mrow_base + (size_t)(row0 + r) * NTOK;
            s[r][0] += mrow[j0];
            s[r][1] += mrow[j1];
            s[r][2] = (lane < 4) ? (s[r][2] + mrow[j2]) : -CUDART_INF_F;
        }

#pragma unroll
        for (int r = 0; r < 4; r++) {
            float mx = fmaxf(fmaxf(s[r][0], s[r][1]), s[r][2]);
#pragma unroll
            for (int off = 16; off > 0; off >>= 1)
                mx = fmaxf(mx, __shfl_xor_sync(0xffffffffu, mx, off));

            const float e0 = __expf(s[r][0] - mx);
            const float e1 = __expf(s[r][1] - mx);
            const float e2 = (lane < 4) ? __expf(s[r][2] - mx) : 0.0f;
            float sum = e0 + e1 + e2;
#pragma unroll
            for (int off = 16; off > 0; off >>= 1)
                sum += __shfl_xor_sync(0xffffffffu, sum, off);
            const float inv = 1.0f / sum;

            sp[warp][r][j0] = e0 * inv;
            sp[warp][r][j1] = e1 * inv;
            if (lane < 4) sp[warp][r][j2] = e2 * inv;
        }
        __syncwarp();

        float o[4][2];
#pragma unroll
        for (int r = 0; r < 4; r++) o[r][0] = o[r][1] = 0.0f;

#pragma unroll
        for (int j = 0; j < NTOK; j++) {
            const float v0 = sv[j][lane];
            const float v1 = sv[j][lane + 32];
#pragma unroll
            for (int r = 0; r < 4; r++) {
                const float p = sp[warp][r][j];
                o[r][0] = fmaf(p, v0, o[r][0]);
                o[r][1] = fmaf(p, v1, o[r][1]);
            }
        }

#pragma unroll
        for (int r = 0; r < 4; r++) {
            const size_t obase = ((size_t)b * NTOK + row0 + r) * C_ + (size_t)h * HD;
            oa[obase + lane]      = __float2half_rn(o[r][0]);
            oa[obase + lane + 32] = __float2half_rn(o[r][1]);
        }
        __syncwarp();
    }
}

// ---------------------------------------------------------------------------
extern "C" void kernel_launch(void* const* d_in, const int* in_sizes, int n_in,
                              void* d_out, int out_size)
{
    const float* x      = (const float*)d_in[0];
    const float* pe     = (const float*)d_in[1];
    const float* mask   = (const float*)d_in[2];
    const float* w_qkv  = (const float*)d_in[3];
    const float* b_qkv  = (const float*)d_in[4];
    const float* w_proj = (const float*)d_in[5];
    const float* b_proj = (const float*)d_in[6];
    float* out = (float*)d_out;

    float* qkv_buf; cudaGetSymbolAddress((void**)&qkv_buf, g_qkv);
    __half *xa, *whi, *wlo, *phi, *plo, *aa;
    cudaGetSymbolAddress((void**)&xa,  g_xa);
    cudaGetSymbolAddress((void**)&whi, g_whi);
    cudaGetSymbolAddress((void**)&wlo, g_wlo);
    cudaGetSymbolAddress((void**)&phi, g_phi);
    cudaGetSymbolAddress((void**)&plo, g_plo);
    cudaGetSymbolAddress((void**)&aa,  g_aa);

    cudaFuncSetAttribute(gemm_f16x2_kernel,
                         cudaFuncAttributeMaxDynamicSharedMemorySize, GEMM_SMEM);

    // 0) precompute fp16 activations + split weights
    {
        const size_t nx = (size_t)M_ * C_ / 4;
        split_x_pe_f16<<<(unsigned)((nx + 255) / 256), 256>>>(x, pe, xa);
        const size_t nw = (size_t)K3C * C_;
        split_w_f16<<<(unsigned)((nw / 4 + 255) / 256), 256>>>(w_qkv, whi, wlo, nw);
        const size_t np = (size_t)C_ * C_;
        split_w_f16<<<(unsigned)((np / 4 + 255) / 256), 256>>>(w_proj, phi, plo, np);
    }

    // 1) QKV projection: (M x 768) @ (768 x 2304)^T + bias -> g_qkv (fp32)
    {
        const int NT = K3C / 128;           // 18
        const int TT = (M_ / 128) * NT;     // 9792
        gemm_f16x2_kernel<<<GEMM_GRID, 256, GEMM_SMEM>>>(
            xa, whi, wlo, b_qkv, qkv_buf, K3C, C_, NT, TT);
    }

    // 2) Attention -> fp16 output
    attention_kernel<<<B_ * H_, 256>>>(qkv_buf, mask, aa);

    // 3) Output projection -> d_out
    {
        const int NT = C_ / 128;            // 6
        const int TT = (M_ / 128) * NT;     // 4080
        gemm_f16x2_kernel<<<GEMM_GRID, 256, GEMM_SMEM>>>(
            aa, phi, plo, b_proj, out, C_, C_, NT, TT);
    }
}

// round 15
// speedup vs baseline: 2.0862x; 1.0234x over previous
#include <cuda_runtime.h>
#include <cuda_fp16.h>
#include <math_constants.h>
#include <cstdint>

// Problem constants
#define B_   1024
#define NTOK 68
#define C_   768
#define H_   12
#define HD   64
#define M_   (B_ * NTOK)        // 69632
#define K3C  (3 * C_)           // 2304

// Scratch (__device__ globals; allocation-free rule)
__device__ float  g_qkv[(size_t)M_ * K3C];   // QKV output fp32
__device__ __half g_xa [(size_t)M_ * C_];    // x+pe, single fp16
__device__ __half g_whi[(size_t)K3C * C_];   // w_qkv split hi
__device__ __half g_wlo[(size_t)K3C * C_];   // w_qkv split lo
__device__ __half g_phi[(size_t)C_ * C_];    // w_proj split hi
__device__ __half g_plo[(size_t)C_ * C_];    // w_proj split lo
__device__ __half g_aa [(size_t)M_ * C_];    // attention out, single fp16

// ---------------------------------------------------------------------------
// helpers
// ---------------------------------------------------------------------------
static __device__ __forceinline__ uint32_t smem_u32(const void* p) {
    uint32_t a;
    asm("{ .reg .u64 t; cvta.to.shared.u64 t, %1; cvt.u32.u64 %0, t; }"
        : "=r"(a) : "l"(p));
    return a;
}

#define CP16(dst, src) \
    asm volatile("cp.async.cg.shared.global [%0], [%1], 16;" \
                 :: "r"(dst), "l"(src))
#define CP_COMMIT() asm volatile("cp.async.commit_group;" ::: "memory")
#define CP_WAIT1()  asm volatile("cp.async.wait_group 1;"  ::: "memory")

#define LDSM_X4(r, addr) \
    asm volatile("ldmatrix.sync.aligned.m8n8.x4.shared.b16 {%0,%1,%2,%3}, [%4];" \
                 : "=r"((r)[0]), "=r"((r)[1]), "=r"((r)[2]), "=r"((r)[3]) \
                 : "r"(addr))

#define MMA_F16(d, a, b0, b1) \
    asm volatile("mma.sync.aligned.m16n8k16.row.col.f32.f16.f16.f32 " \
                 "{%0,%1,%2,%3}, {%4,%5,%6,%7}, {%8,%9}, {%0,%1,%2,%3};" \
                 : "+f"((d)[0]), "+f"((d)[1]), "+f"((d)[2]), "+f"((d)[3]) \
                 : "r"((a)[0]), "r"((a)[1]), "r"((a)[2]), "r"((a)[3]), \
                   "r"(b0), "r"(b1))

// packed fp32x2 FMA (sm_100-family): d = a*b + d elementwise on fp32 pairs
#define FFMA2(d, a, b) \
    asm("fma.rn.f32x2 %0, %1, %2, %0;" : "+l"(d) : "l"(a), "l"(b))
#define UNPACK2(lo, hi, v) \
    asm("mov.b64 {%0, %1}, %2;" : "=f"(lo), "=f"(hi) : "l"(v))
#define DUP2(d, s) \
    asm("mov.b64 %0, {%1, %1};" : "=l"(d) : "f"(s))

// smem tile: 128 rows x 128 bytes (64 fp16 = one K-chunk of 64), canonical
// SW128 swizzle. 2 stages x 3 tiles (A, Bhi, Blo) x 16KB = 96KB -> 2 CTAs/SM.
static __device__ __forceinline__ uint32_t swf(int row, int c16) {
    return (uint32_t)(row * 128 + (((c16 ^ row) & 7) << 4));
}
#define TILE_ST(s, w) ((s) * 49152 + (w) * 16384)
#define GEMM_SMEM 98304
#define GEMM_GRID 1184

// ---------------------------------------------------------------------------
// split kernels
// ---------------------------------------------------------------------------
__global__ void split_x_pe_f16(const float* __restrict__ x,
                               const float* __restrict__ pe,
                               __half* __restrict__ a)
{
    const size_t i4 = (size_t)blockIdx.x * blockDim.x + threadIdx.x;
    const size_t e  = i4 * 4;
    if (e >= (size_t)M_ * C_) return;
    const int row = (int)(e / C_);
    const int col = (int)(e % C_);
    const int tok = row % NTOK;

    float4 v = *reinterpret_cast<const float4*>(x + e);
    if (tok >= 4) {
        const float4 p = *reinterpret_cast<const float4*>(
            pe + (size_t)(tok + 28) * C_ + col);
        v.x += p.x; v.y += p.y; v.z += p.z; v.w += p.w;
    }
    __half2* ap = reinterpret_cast<__half2*>(a + e);
    ap[0] = __half2(__float2half_rn(v.x), __float2half_rn(v.y));
    ap[1] = __half2(__float2half_rn(v.z), __float2half_rn(v.w));
}

__global__ void split_w_f16(const float* __restrict__ w,
                            __half* __restrict__ hi,
                            __half* __restrict__ lo,
                            size_t n_elem)
{
    const size_t i4 = (size_t)blockIdx.x * blockDim.x + threadIdx.x;
    const size_t e  = i4 * 4;
    if (e >= n_elem) return;
    const float4 v = *reinterpret_cast<const float4*>(w + e);
    __half h0 = __float2half_rn(v.x), l0 = __float2half_rn(v.x - __half2float(h0));
    __half h1 = __float2half_rn(v.y), l1 = __float2half_rn(v.y - __half2float(h1));
    __half h2 = __float2half_rn(v.z), l2 = __float2half_rn(v.z - __half2float(h2));
    __half h3 = __float2half_rn(v.w), l3 = __float2half_rn(v.w - __half2float(h3));
    __half2* hp = reinterpret_cast<__half2*>(hi + e);
    __half2* lp = reinterpret_cast<__half2*>(lo + e);
    hp[0] = __half2(h0, h1); hp[1] = __half2(h2, h3);
    lp[0] = __half2(l0, l1); lp[1] = __half2(l2, l3);
}

// ---------------------------------------------------------------------------
// Persistent GEMM (unchanged from round 14): C = A·W^T + bias,
// D = A*Bhi + A*Blo (fp16 mma, fp32 acc). 2-stage ring, 2 CTAs/SM.
// ---------------------------------------------------------------------------
__global__ __launch_bounds__(256, 2)
void gemm_f16x2_kernel(const __half* __restrict__ A,
                       const __half* __restrict__ Bhi,
                       const __half* __restrict__ Blo,
                       const float* __restrict__ bias,
                       float* __restrict__ Cout,
                       int N, int K, int NT, int TT)
{
    extern __shared__ char smem[];
    const uint32_t sb = smem_u32(smem);

    const int tid  = threadIdx.x;
    const int wid  = tid >> 5;
    const int lane = tid & 31;
    const int wm   = wid & 1;    // 0..1
    const int wn   = wid >> 1;   // 0..3

    const int r0  = tid >> 3, c16 = tid & 7;
    const uint32_t so = swf(r0, c16);

#define TILE_OFFSETS(lt_, ao_, bo_)                                   \
    do {                                                              \
        const int cN_ = (lt_) % NT, cM_ = (lt_) / NT;                 \
        ao_ = (size_t)(cM_ * 128 + r0) * K + c16 * 8;                 \
        bo_ = (size_t)(cN_ * 128 + r0) * K + c16 * 8;                 \
    } while (0)

#define LOAD_STAGE(s, ao_, bo_, k0)                                          \
    do {                                                                      \
        _Pragma("unroll")                                                     \
        for (int i = 0; i < 4; i++) {                                         \
            const uint32_t d = so + 4096u * i;                                \
            const size_t   g = (size_t)(32 * i) * K + (k0);                   \
            CP16(sb + TILE_ST(s, 0) + d, A   + (ao_) + g);                    \
            CP16(sb + TILE_ST(s, 1) + d, Bhi + (bo_) + g);                    \
            CP16(sb + TILE_ST(s, 2) + d, Blo + (bo_) + g);                    \
        }                                                                     \
    } while (0)

    const int arow = wm * 64 + (lane & 15);
    const int brow = wn * 32 + (lane & 15);
    const int chi  = lane >> 4;

#define FRAG_LOAD(st, t)                                                     \
    do {                                                                      \
        _Pragma("unroll")                                                     \
        for (int mf = 0; mf < 4; mf++) {                                      \
            const uint32_t ao_ = swf(arow + mf * 16, 2 * (t) + chi);          \
            LDSM_X4(Aa[mf], sb + TILE_ST(st, 0) + ao_);                       \
        }                                                                     \
        _Pragma("unroll")                                                     \
        for (int bf = 0; bf < 2; bf++) {                                      \
            const uint32_t bo_ = swf(brow + bf * 16, 2 * (t) + chi);          \
            LDSM_X4(Bh[bf], sb + TILE_ST(st, 1) + bo_);                       \
            LDSM_X4(Bl[bf], sb + TILE_ST(st, 2) + bo_);                       \
        }                                                                     \
    } while (0)

#define MMA_ALL()                                                            \
    do {                                                                      \
        _Pragma("unroll")                                                     \
        for (int mf = 0; mf < 4; mf++) {                                      \
            _Pragma("unroll")                                                 \
            for (int nf = 0; nf < 4; nf++) {                                  \
                const int g = nf >> 1, h = nf & 1;                            \
                MMA_F16(acc[mf][nf], Aa[mf], Bh[g][h], Bh[g][h + 2]);         \
            }                                                                 \
        }                                                                     \
        _Pragma("unroll")                                                     \
        for (int mf = 0; mf < 4; mf++) {                                      \
            _Pragma("unroll")                                                 \
            for (int nf = 0; nf < 4; nf++) {                                  \
                const int g = nf >> 1, h = nf & 1;                            \
                MMA_F16(acc[mf][nf], Aa[mf], Bl[g][h], Bl[g][h + 2]);         \
            }                                                                 \
        }                                                                     \
    } while (0)

    float acc[4][4][4];
#pragma unroll
    for (int i = 0; i < 4; i++)
#pragma unroll
        for (int j = 0; j < 4; j++)
#pragma unroll
            for (int r = 0; r < 4; r++) acc[i][j][r] = 0.0f;

    const int NC = K >> 6;   // 12 (even)

    uint32_t Aa[4][4], Bh[2][4], Bl[2][4];

    int lt = blockIdx.x;
    if (lt >= TT) return;

    size_t ao, bo;
    TILE_OFFSETS(lt, ao, bo);

    LOAD_STAGE(0, ao, bo, 0);    CP_COMMIT();
    LOAD_STAGE(1, ao, bo, 64);   CP_COMMIT();
    CP_WAIT1();
    __syncthreads();

    for (;;) {
        for (int kc = 0; kc < NC; kc++) {
            const int cur = kc & 1;

            FRAG_LOAD(cur, 0); MMA_ALL();
            FRAG_LOAD(cur, 1); MMA_ALL();
            FRAG_LOAD(cur, 2); MMA_ALL();
            FRAG_LOAD(cur, 3); MMA_ALL();

            __syncthreads();

            const int rc = kc + 2;
            if (rc < NC) {
                LOAD_STAGE(cur, ao, bo, rc * 64);
            } else {
                const int ltn = lt + (int)gridDim.x;
                if (ltn < TT) {
                    size_t nao, nbo;
                    TILE_OFFSETS(ltn, nao, nbo);
                    LOAD_STAGE(cur, nao, nbo, (rc - NC) * 64);
                }
            }
            CP_COMMIT();

            CP_WAIT1();
            __syncthreads();
        }

        {
            const int cN = lt % NT, cM = lt / NT;
#pragma unroll
            for (int mf = 0; mf < 4; mf++) {
                const int row = cM * 128 + wm * 64 + mf * 16 + (lane >> 2);
#pragma unroll
                for (int nf = 0; nf < 4; nf++) {
                    const int col = cN * 128 + wn * 32 + nf * 8 + (lane & 3) * 2;
                    const float2 bb = *reinterpret_cast<const float2*>(bias + col);
                    float2 o0, o1;
                    o0.x = acc[mf][nf][0] + bb.x;  o0.y = acc[mf][nf][1] + bb.y;
                    o1.x = acc[mf][nf][2] + bb.x;  o1.y = acc[mf][nf][3] + bb.y;
                    *reinterpret_cast<float2*>(Cout + (size_t)row * N + col) = o0;
                    *reinterpret_cast<float2*>(Cout + (size_t)(row + 8) * N + col) = o1;
                }
            }
        }
#pragma unroll
        for (int i = 0; i < 4; i++)
#pragma unroll
            for (int j = 0; j < 4; j++)
#pragma unroll
                for (int r = 0; r < 4; r++) acc[i][j][r] = 0.0f;

        lt += (int)gridDim.x;
        if (lt >= TT) break;
        TILE_OFFSETS(lt, ao, bo);
    }
#undef TILE_OFFSETS
#undef LOAD_STAGE
#undef FRAG_LOAD
#undef MMA_ALL
}

// ---------------------------------------------------------------------------
// Attention (FFMA2 / fp32x2 version): one CTA per (b, h), 4 q-rows per warp.
// d-paired layout: ld.shared.b64 pulls fp32 pairs straight into packed regs,
// fma.rn.f32x2 does 2 FMAs per instruction -> crossbar cycles ~0.6x, FMA
// issue ~0.5x vs the scalar version. Writes single fp16 output (contiguous:
// lane owns d = 2*lane, 2*lane+1).
// ---------------------------------------------------------------------------
typedef unsigned long long u64;

__global__ __launch_bounds__(256)
void attention_kernel(const float* __restrict__ qkv,
                      const float* __restrict__ mask,
                      __half* __restrict__ oa)
{
    __shared__ float sk[NTOK][HD + 2];        // stride 66 floats: 8B-aligned rows
    __shared__ float sv2[NTOK][HD];           // row j: (v[2l],v[2l+1]) pairs, 256B/row
    __shared__ float sq[8][4][HD];            // 256B rows -> .b64 reads aligned
    __shared__ float sp[8][4][NTOK];

    const int bh = blockIdx.x;
    const int b  = bh / H_;
    const int h  = bh % H_;
    const int tid  = threadIdx.x;
    const int warp = tid >> 5;
    const int lane = tid & 31;

    const size_t base = (size_t)b * NTOK * K3C + (size_t)h * HD;
    // stage K (scalar layout) and V (d-pair layout)
    for (int idx = tid; idx < NTOK * HD; idx += 256) {
        const int j = idx / HD, d = idx % HD;
        sk[j][d] = qkv[base + (size_t)j * K3C + C_ + d];
    }
    for (int idx = tid; idx < NTOK * (HD / 2); idx += 256) {
        const int j = idx / (HD / 2), l = idx % (HD / 2);
        const float2 v = *reinterpret_cast<const float2*>(
            qkv + base + (size_t)j * K3C + 2 * C_ + 2 * l);
        *reinterpret_cast<float2*>(&sv2[j][2 * l]) = v;
    }
    __syncthreads();

    const float scale = 0.125f;
    const float* mrow_base = mask + (size_t)b * NTOK * NTOK;
    const int j0 = lane;
    const int j1 = lane + 32;
    const int j2 = (lane < 4) ? lane + 64 : 67;   // clamped; masked below

    for (int g = warp; g < 17; g += 8) {
        const int row0 = g * 4;

#pragma unroll
        for (int r = 0; r < 4; r++) {
            sq[warp][r][lane]      = qkv[base + (size_t)(row0 + r) * K3C + lane]      * scale;
            sq[warp][r][lane + 32] = qkv[base + (size_t)(row0 + r) * K3C + lane + 32] * scale;
        }
        __syncwarp();

        // scores: packed partial sums over d-pairs
        u64 s2[4][3];
#pragma unroll
        for (int r = 0; r < 4; r++)
            s2[r][0] = s2[r][1] = s2[r][2] = 0ull;

        const u64* q0 = reinterpret_cast<const u64*>(sq[warp][0]);
        const u64* q1 = reinterpret_cast<const u64*>(sq[warp][1]);
        const u64* q2p = reinterpret_cast<const u64*>(sq[warp][2]);
        const u64* q3 = reinterpret_cast<const u64*>(sq[warp][3]);

#pragma unroll
        for (int dp = 0; dp < HD / 2; dp++) {
            const u64 k0 = *reinterpret_cast<const u64*>(&sk[j0][2 * dp]);
            const u64 k1 = *reinterpret_cast<const u64*>(&sk[j1][2 * dp]);
            const u64 k2 = *reinterpret_cast<const u64*>(&sk[j2][2 * dp]);
            const u64 qq0 = q0[dp], qq1 = q1[dp], qq2 = q2p[dp], qq3 = q3[dp];
            FFMA2(s2[0][0], qq0, k0); FFMA2(s2[0][1], qq0, k1); FFMA2(s2[0][2], qq0, k2);
            FFMA2(s2[1][0], qq1, k0); FFMA2(s2[1][1], qq1, k1); FFMA2(s2[1][2], qq1, k2);
            FFMA2(s2[2][0], qq2, k0); FFMA2(s2[2][1], qq2, k1); FFMA2(s2[2][2], qq2, k2);
            FFMA2(s2[3][0], qq3, k0); FFMA2(s2[3][1], qq3, k1); FFMA2(s2[3][2], qq3, k2);
        }

        float s[4][3];
#pragma unroll
        for (int r = 0; r < 4; r++) {
#pragma unroll
            for (int t = 0; t < 3; t++) {
                float lo, hi;
                UNPACK2(lo, hi, s2[r][t]);
                s[r][t] = lo + hi;
            }
            const float* mrow = mrow_base + (size_t)(row0 + r) * NTOK;
            s[r][0] += mrow[j0];
            s[r][1] += mrow[j1];
            s[r][2] = (lane < 4) ? (s[r][2] + mrow[j2]) : -CUDART_INF_F;
        }

        // softmax per row
#pragma unroll
        for (int r = 0; r < 4; r++) {
            float mx = fmaxf(fmaxf(s[r][0], s[r][1]), s[r][2]);
#pragma unroll
            for (int off = 16; off > 0; off >>= 1)
                mx = fmaxf(mx, __shfl_xor_sync(0xffffffffu, mx, off));

            const float e0 = __expf(s[r][0] - mx);
            const float e1 = __expf(s[r][1] - mx);
            const float e2 = (lane < 4) ? __expf(s[r][2] - mx) : 0.0f;
            float sum = e0 + e1 + e2;
#pragma unroll
            for (int off = 16; off > 0; off >>= 1)
                sum += __shfl_xor_sync(0xffffffffu, sum, off);
            const float inv = 1.0f / sum;

            sp[warp][r][j0] = e0 * inv;
            sp[warp][r][j1] = e1 * inv;
            if (lane < 4) sp[warp][r][j2] = e2 * inv;
        }
        __syncwarp();

        // PV: lane owns d-pair (2*lane, 2*lane+1); packed accumulate over j
        u64 o2[4];
#pragma unroll
        for (int r = 0; r < 4; r++) o2[r] = 0ull;

#pragma unroll
        for (int j = 0; j < NTOK; j++) {
            const u64 vv = *reinterpret_cast<const u64*>(&sv2[j][2 * lane]);
            u64 pp0, pp1, pp2, pp3;
            DUP2(pp0, sp[warp][0][j]);
            DUP2(pp1, sp[warp][1][j]);
            DUP2(pp2, sp[warp][2][j]);
            DUP2(pp3, sp[warp][3][j]);
            FFMA2(o2[0], vv, pp0);
            FFMA2(o2[1], vv, pp1);
            FFMA2(o2[2], vv, pp2);
            FFMA2(o2[3], vv, pp3);
        }

#pragma unroll
        for (int r = 0; r < 4; r++) {
            float lo, hi;
            UNPACK2(lo, hi, o2[r]);
            const size_t obase = ((size_t)b * NTOK + row0 + r) * C_ + (size_t)h * HD;
            *reinterpret_cast<__half2*>(oa + obase + 2 * lane) =
                __half2(__float2half_rn(lo), __float2half_rn(hi));
        }
        __syncwarp();
    }
}

// ---------------------------------------------------------------------------
extern "C" void kernel_launch(void* const* d_in, const int* in_sizes, int n_in,
                              void* d_out, int out_size)
{
    const float* x      = (const float*)d_in[0];
    const float* pe     = (const float*)d_in[1];
    const float* mask   = (const float*)d_in[2];
    const float* w_qkv  = (const float*)d_in[3];
    const float* b_qkv  = (const float*)d_in[4];
    const float* w_proj = (const float*)d_in[5];
    const float* b_proj = (const float*)d_in[6];
    float* out = (float*)d_out;

    float* qkv_buf; cudaGetSymbolAddress((void**)&qkv_buf, g_qkv);
    __half *xa, *whi, *wlo, *phi, *plo, *aa;
    cudaGetSymbolAddress((void**)&xa,  g_xa);
    cudaGetSymbolAddress((void**)&whi, g_whi);
    cudaGetSymbolAddress((void**)&wlo, g_wlo);
    cudaGetSymbolAddress((void**)&phi, g_phi);
    cudaGetSymbolAddress((void**)&plo, g_plo);
    cudaGetSymbolAddress((void**)&aa,  g_aa);

    cudaFuncSetAttribute(gemm_f16x2_kernel,
                         cudaFuncAttributeMaxDynamicSharedMemorySize, GEMM_SMEM);

    // 0) precompute fp16 activations + split weights
    {
        const size_t nx = (size_t)M_ * C_ / 4;
        split_x_pe_f16<<<(unsigned)((nx + 255) / 256), 256>>>(x, pe, xa);
        const size_t nw = (size_t)K3C * C_;
        split_w_f16<<<(unsigned)((nw / 4 + 255) / 256), 256>>>(w_qkv, whi, wlo, nw);
        const size_t np = (size_t)C_ * C_;
        split_w_f16<<<(unsigned)((np / 4 + 255) / 256), 256>>>(w_proj, phi, plo, np);
    }

    // 1) QKV projection: (M x 768) @ (768 x 2304)^T + bias -> g_qkv (fp32)
    {
        const int NT = K3C / 128;           // 18
        const int TT = (M_ / 128) * NT;     // 9792
        gemm_f16x2_kernel<<<GEMM_GRID, 256, GEMM_SMEM>>>(
            xa, whi, wlo, b_qkv, qkv_buf, K3C, C_, NT, TT);
    }

    // 2) Attention -> fp16 output
    attention_kernel<<<B_ * H_, 256>>>(qkv_buf, mask, aa);

    // 3) Output projection -> d_out
    {
        const int NT = C_ / 128;            // 6
        const int TT = (M_ / 128) * NT;     // 4080
        gemm_f16x2_kernel<<<GEMM_GRID, 256, GEMM_SMEM>>>(
            aa, phi, plo, b_proj, out, C_, C_, NT, TT);
    }
}

// round 16
// speedup vs baseline: 2.1252x; 1.0187x over previous
#include <cuda_runtime.h>
#include <cuda_fp16.h>
#include <math_constants.h>
#include <cstdint>

// Problem constants
#define B_   1024
#define NTOK 68
#define C_   768
#define H_   12
#define HD   64
#define M_   (B_ * NTOK)        // 69632
#define K3C  (3 * C_)           // 2304

// Scratch (__device__ globals; allocation-free rule)
__device__ float  g_qkv[(size_t)M_ * K3C];   // QKV output fp32
__device__ __half g_xa [(size_t)M_ * C_];    // x+pe, single fp16
__device__ __half g_whi[(size_t)K3C * C_];   // w_qkv split hi
__device__ __half g_wlo[(size_t)K3C * C_];   // w_qkv split lo
__device__ __half g_phi[(size_t)C_ * C_];    // w_proj split hi
__device__ __half g_plo[(size_t)C_ * C_];    // w_proj split lo
__device__ __half g_aa [(size_t)M_ * C_];    // attention out, single fp16

// ---------------------------------------------------------------------------
// helpers
// ---------------------------------------------------------------------------
static __device__ __forceinline__ uint32_t smem_u32(const void* p) {
    uint32_t a;
    asm("{ .reg .u64 t; cvta.to.shared.u64 t, %1; cvt.u32.u64 %0, t; }"
        : "=r"(a) : "l"(p));
    return a;
}

#define CP16(dst, src) \
    asm volatile("cp.async.cg.shared.global [%0], [%1], 16;" \
                 :: "r"(dst), "l"(src))
#define CP_COMMIT() asm volatile("cp.async.commit_group;" ::: "memory")
#define CP_WAIT1()  asm volatile("cp.async.wait_group 1;"  ::: "memory")

#define LDSM_X4(r, addr) \
    asm volatile("ldmatrix.sync.aligned.m8n8.x4.shared.b16 {%0,%1,%2,%3}, [%4];" \
                 : "=r"((r)[0]), "=r"((r)[1]), "=r"((r)[2]), "=r"((r)[3]) \
                 : "r"(addr))

#define MMA_F16(d, a, b0, b1) \
    asm volatile("mma.sync.aligned.m16n8k16.row.col.f32.f16.f16.f32 " \
                 "{%0,%1,%2,%3}, {%4,%5,%6,%7}, {%8,%9}, {%0,%1,%2,%3};" \
                 : "+f"((d)[0]), "+f"((d)[1]), "+f"((d)[2]), "+f"((d)[3]) \
                 : "r"((a)[0]), "r"((a)[1]), "r"((a)[2]), "r"((a)[3]), \
                   "r"(b0), "r"(b1))

// packed fp32x2 FMA (sm_100-family): d = a*b + d elementwise on fp32 pairs
#define FFMA2(d, a, b) \
    asm("fma.rn.f32x2 %0, %1, %2, %0;" : "+l"(d) : "l"(a), "l"(b))
#define UNPACK2(lo, hi, v) \
    asm("mov.b64 {%0, %1}, %2;" : "=f"(lo), "=f"(hi) : "l"(v))
#define DUP2(d, s) \
    asm("mov.b64 %0, {%1, %1};" : "=l"(d) : "f"(s))

// smem tile: 128 rows x 128 bytes (64 fp16 = one K-chunk of 64), canonical
// SW128 swizzle. 2 stages x 3 tiles (A, Bhi, Blo) x 16KB = 96KB -> 2 CTAs/SM.
static __device__ __forceinline__ uint32_t swf(int row, int c16) {
    return (uint32_t)(row * 128 + (((c16 ^ row) & 7) << 4));
}
#define TILE_ST(s, w) ((s) * 49152 + (w) * 16384)
#define GEMM_SMEM 98304
#define GEMM_GRID 1184

// ---------------------------------------------------------------------------
// split kernels
// ---------------------------------------------------------------------------
__global__ void split_x_pe_f16(const float* __restrict__ x,
                               const float* __restrict__ pe,
                               __half* __restrict__ a)
{
    const size_t i4 = (size_t)blockIdx.x * blockDim.x + threadIdx.x;
    const size_t e  = i4 * 4;
    if (e >= (size_t)M_ * C_) return;
    const int row = (int)(e / C_);
    const int col = (int)(e % C_);
    const int tok = row % NTOK;

    float4 v = *reinterpret_cast<const float4*>(x + e);
    if (tok >= 4) {
        const float4 p = *reinterpret_cast<const float4*>(
            pe + (size_t)(tok + 28) * C_ + col);
        v.x += p.x; v.y += p.y; v.z += p.z; v.w += p.w;
    }
    __half2* ap = reinterpret_cast<__half2*>(a + e);
    ap[0] = __half2(__float2half_rn(v.x), __float2half_rn(v.y));
    ap[1] = __half2(__float2half_rn(v.z), __float2half_rn(v.w));
}

__global__ void split_w_f16(const float* __restrict__ w,
                            __half* __restrict__ hi,
                            __half* __restrict__ lo,
                            size_t n_elem)
{
    const size_t i4 = (size_t)blockIdx.x * blockDim.x + threadIdx.x;
    const size_t e  = i4 * 4;
    if (e >= n_elem) return;
    const float4 v = *reinterpret_cast<const float4*>(w + e);
    __half h0 = __float2half_rn(v.x), l0 = __float2half_rn(v.x - __half2float(h0));
    __half h1 = __float2half_rn(v.y), l1 = __float2half_rn(v.y - __half2float(h1));
    __half h2 = __float2half_rn(v.z), l2 = __float2half_rn(v.z - __half2float(h2));
    __half h3 = __float2half_rn(v.w), l3 = __float2half_rn(v.w - __half2float(h3));
    __half2* hp = reinterpret_cast<__half2*>(hi + e);
    __half2* lp = reinterpret_cast<__half2*>(lo + e);
    hp[0] = __half2(h0, h1); hp[1] = __half2(h2, h3);
    lp[0] = __half2(l0, l1); lp[1] = __half2(l2, l3);
}

// ---------------------------------------------------------------------------
// Persistent GEMM (unchanged from round 14/15): C = A·W^T + bias,
// D = A*Bhi + A*Blo (fp16 mma, fp32 acc). 2-stage ring, 2 CTAs/SM.
// ---------------------------------------------------------------------------
__global__ __launch_bounds__(256, 2)
void gemm_f16x2_kernel(const __half* __restrict__ A,
                       const __half* __restrict__ Bhi,
                       const __half* __restrict__ Blo,
                       const float* __restrict__ bias,
                       float* __restrict__ Cout,
                       int N, int K, int NT, int TT)
{
    extern __shared__ char smem[];
    const uint32_t sb = smem_u32(smem);

    const int tid  = threadIdx.x;
    const int wid  = tid >> 5;
    const int lane = tid & 31;
    const int wm   = wid & 1;    // 0..1
    const int wn   = wid >> 1;   // 0..3

    const int r0  = tid >> 3, c16 = tid & 7;
    const uint32_t so = swf(r0, c16);

#define TILE_OFFSETS(lt_, ao_, bo_)                                   \
    do {                                                              \
        const int cN_ = (lt_) % NT, cM_ = (lt_) / NT;                 \
        ao_ = (size_t)(cM_ * 128 + r0) * K + c16 * 8;                 \
        bo_ = (size_t)(cN_ * 128 + r0) * K + c16 * 8;                 \
    } while (0)

#define LOAD_STAGE(s, ao_, bo_, k0)                                          \
    do {                                                                      \
        _Pragma("unroll")                                                     \
        for (int i = 0; i < 4; i++) {                                         \
            const uint32_t d = so + 4096u * i;                                \
            const size_t   g = (size_t)(32 * i) * K + (k0);                   \
            CP16(sb + TILE_ST(s, 0) + d, A   + (ao_) + g);                    \
            CP16(sb + TILE_ST(s, 1) + d, Bhi + (bo_) + g);                    \
            CP16(sb + TILE_ST(s, 2) + d, Blo + (bo_) + g);                    \
        }                                                                     \
    } while (0)

    const int arow = wm * 64 + (lane & 15);
    const int brow = wn * 32 + (lane & 15);
    const int chi  = lane >> 4;

#define FRAG_LOAD(st, t)                                                     \
    do {                                                                      \
        _Pragma("unroll")                                                     \
        for (int mf = 0; mf < 4; mf++) {                                      \
            const uint32_t ao_ = swf(arow + mf * 16, 2 * (t) + chi);          \
            LDSM_X4(Aa[mf], sb + TILE_ST(st, 0) + ao_);                       \
        }                                                                     \
        _Pragma("unroll")                                                     \
        for (int bf = 0; bf < 2; bf++) {                                      \
            const uint32_t bo_ = swf(brow + bf * 16, 2 * (t) + chi);          \
            LDSM_X4(Bh[bf], sb + TILE_ST(st, 1) + bo_);                       \
            LDSM_X4(Bl[bf], sb + TILE_ST(st, 2) + bo_);                       \
        }                                                                     \
    } while (0)

#define MMA_ALL()                                                            \
    do {                                                                      \
        _Pragma("unroll")                                                     \
        for (int mf = 0; mf < 4; mf++) {                                      \
            _Pragma("unroll")                                                 \
            for (int nf = 0; nf < 4; nf++) {                                  \
                const int g = nf >> 1, h = nf & 1;                            \
                MMA_F16(acc[mf][nf], Aa[mf], Bh[g][h], Bh[g][h + 2]);         \
            }                                                                 \
        }                                                                     \
        _Pragma("unroll")                                                     \
        for (int mf = 0; mf < 4; mf++) {                                      \
            _Pragma("unroll")                                                 \
            for (int nf = 0; nf < 4; nf++) {                                  \
                const int g = nf >> 1, h = nf & 1;                            \
                MMA_F16(acc[mf][nf], Aa[mf], Bl[g][h], Bl[g][h + 2]);         \
            }                                                                 \
        }                                                                     \
    } while (0)

    float acc[4][4][4];
#pragma unroll
    for (int i = 0; i < 4; i++)
#pragma unroll
        for (int j = 0; j < 4; j++)
#pragma unroll
            for (int r = 0; r < 4; r++) acc[i][j][r] = 0.0f;

    const int NC = K >> 6;   // 12 (even)

    uint32_t Aa[4][4], Bh[2][4], Bl[2][4];

    int lt = blockIdx.x;
    if (lt >= TT) return;

    size_t ao, bo;
    TILE_OFFSETS(lt, ao, bo);

    LOAD_STAGE(0, ao, bo, 0);    CP_COMMIT();
    LOAD_STAGE(1, ao, bo, 64);   CP_COMMIT();
    CP_WAIT1();
    __syncthreads();

    for (;;) {
        for (int kc = 0; kc < NC; kc++) {
            const int cur = kc & 1;

            FRAG_LOAD(cur, 0); MMA_ALL();
            FRAG_LOAD(cur, 1); MMA_ALL();
            FRAG_LOAD(cur, 2); MMA_ALL();
            FRAG_LOAD(cur, 3); MMA_ALL();

            __syncthreads();

            const int rc = kc + 2;
            if (rc < NC) {
                LOAD_STAGE(cur, ao, bo, rc * 64);
            } else {
                const int ltn = lt + (int)gridDim.x;
                if (ltn < TT) {
                    size_t nao, nbo;
                    TILE_OFFSETS(ltn, nao, nbo);
                    LOAD_STAGE(cur, nao, nbo, (rc - NC) * 64);
                }
            }
            CP_COMMIT();

            CP_WAIT1();
            __syncthreads();
        }

        {
            const int cN = lt % NT, cM = lt / NT;
#pragma unroll
            for (int mf = 0; mf < 4; mf++) {
                const int row = cM * 128 + wm * 64 + mf * 16 + (lane >> 2);
#pragma unroll
                for (int nf = 0; nf < 4; nf++) {
                    const int col = cN * 128 + wn * 32 + nf * 8 + (lane & 3) * 2;
                    const float2 bb = *reinterpret_cast<const float2*>(bias + col);
                    float2 o0, o1;
                    o0.x = acc[mf][nf][0] + bb.x;  o0.y = acc[mf][nf][1] + bb.y;
                    o1.x = acc[mf][nf][2] + bb.x;  o1.y = acc[mf][nf][3] + bb.y;
                    *reinterpret_cast<float2*>(Cout + (size_t)row * N + col) = o0;
                    *reinterpret_cast<float2*>(Cout + (size_t)(row + 8) * N + col) = o1;
                }
            }
        }
#pragma unroll
        for (int i = 0; i < 4; i++)
#pragma unroll
            for (int j = 0; j < 4; j++)
#pragma unroll
                for (int r = 0; r < 4; r++) acc[i][j][r] = 0.0f;

        lt += (int)gridDim.x;
        if (lt >= TT) break;
        TILE_OFFSETS(lt, ao, bo);
    }
#undef TILE_OFFSETS
#undef LOAD_STAGE
#undef FRAG_LOAD
#undef MMA_ALL
}

// ---------------------------------------------------------------------------
// Attention (FFMA2, bank-swizzled K): one CTA per (b, h), 4 q-rows per warp.
// K stored as u64 pairs skp[j][dp ^ ((j>>4)&1)] -> lanes l and l+16 (rows
// differing in bit 4) hit different banks: conflict-free LDS.64 for all
// three key slots. sv2 PV loads are same-row consecutive (conflict-free);
// sq reads are uniform-address broadcasts (free).
// ---------------------------------------------------------------------------
typedef unsigned long long u64;

__global__ __launch_bounds__(256)
void attention_kernel(const float* __restrict__ qkv,
                      const float* __restrict__ mask,
                      __half* __restrict__ oa)
{
    __shared__ u64   skp[NTOK][33];           // 33-u64 rows; col swizzled by row bit 4
    __shared__ float sv2[NTOK][HD];           // row j: (v[2l],v[2l+1]) pairs
    __shared__ float sq[8][4][HD];
    __shared__ float sp[8][4][NTOK];

    const int bh = blockIdx.x;
    const int b  = bh / H_;
    const int h  = bh % H_;
    const int tid  = threadIdx.x;
    const int warp = tid >> 5;
    const int lane = tid & 31;

    const size_t base = (size_t)b * NTOK * K3C + (size_t)h * HD;
    // stage K (pair layout, bank-swizzled) and V (pair layout)
    for (int idx = tid; idx < NTOK * (HD / 2); idx += 256) {
        const int j = idx / (HD / 2), l = idx % (HD / 2);
        const float2 kv = *reinterpret_cast<const float2*>(
            qkv + base + (size_t)j * K3C + C_ + 2 * l);
        u64 pk;
        asm("mov.b64 %0, {%1, %2};" : "=l"(pk) : "f"(kv.x), "f"(kv.y));
        skp[j][l ^ ((j >> 4) & 1)] = pk;
        const float2 v = *reinterpret_cast<const float2*>(
            qkv + base + (size_t)j * K3C + 2 * C_ + 2 * l);
        *reinterpret_cast<float2*>(&sv2[j][2 * l]) = v;
    }
    __syncthreads();

    const float scale = 0.125f;
    const float* mrow_base = mask + (size_t)b * NTOK * NTOK;
    const int j0 = lane;
    const int j1 = lane + 32;
    const int j2 = (lane < 4) ? lane + 64 : 67;   // clamped; masked below

    // per-lane swizzle bits for the three key rows
    const int sw0 = (j0 >> 4) & 1;
    const int sw1 = (j1 >> 4) & 1;
    const int sw2 = (j2 >> 4) & 1;

    for (int g = warp; g < 17; g += 8) {
        const int row0 = g * 4;

#pragma unroll
        for (int r = 0; r < 4; r++) {
            sq[warp][r][lane]      = qkv[base + (size_t)(row0 + r) * K3C + lane]      * scale;
            sq[warp][r][lane + 32] = qkv[base + (size_t)(row0 + r) * K3C + lane + 32] * scale;
        }
        __syncwarp();

        // scores: packed partial sums over d-pairs
        u64 s2[4][3];
#pragma unroll
        for (int r = 0; r < 4; r++)
            s2[r][0] = s2[r][1] = s2[r][2] = 0ull;

        const u64* q0 = reinterpret_cast<const u64*>(sq[warp][0]);
        const u64* q1 = reinterpret_cast<const u64*>(sq[warp][1]);
        const u64* q2p = reinterpret_cast<const u64*>(sq[warp][2]);
        const u64* q3 = reinterpret_cast<const u64*>(sq[warp][3]);

#pragma unroll
        for (int dp = 0; dp < HD / 2; dp++) {
            const u64 k0 = skp[j0][dp ^ sw0];
            const u64 k1 = skp[j1][dp ^ sw1];
            const u64 k2 = skp[j2][dp ^ sw2];
            const u64 qq0 = q0[dp], qq1 = q1[dp], qq2 = q2p[dp], qq3 = q3[dp];
            FFMA2(s2[0][0], qq0, k0); FFMA2(s2[0][1], qq0, k1); FFMA2(s2[0][2], qq0, k2);
            FFMA2(s2[1][0], qq1, k0); FFMA2(s2[1][1], qq1, k1); FFMA2(s2[1][2], qq1, k2);
            FFMA2(s2[2][0], qq2, k0); FFMA2(s2[2][1], qq2, k1); FFMA2(s2[2][2], qq2, k2);
            FFMA2(s2[3][0], qq3, k0); FFMA2(s2[3][1], qq3, k1); FFMA2(s2[3][2], qq3, k2);
        }

        float s[4][3];
#pragma unroll
        for (int r = 0; r < 4; r++) {
#pragma unroll
            for (int t = 0; t < 3; t++) {
                float lo, hi;
                UNPACK2(lo, hi, s2[r][t]);
                s[r][t] = lo + hi;
            }
            const float* mrow = mrow_base + (size_t)(row0 + r) * NTOK;
            s[r][0] += mrow[j0];
            s[r][1] += mrow[j1];
            s[r][2] = (lane < 4) ? (s[r][2] + mrow[j2]) : -CUDART_INF_F;
        }

        // softmax per row
#pragma unroll
        for (int r = 0; r < 4; r++) {
            float mx = fmaxf(fmaxf(s[r][0], s[r][1]), s[r][2]);
#pragma unroll
            for (int off = 16; off > 0; off >>= 1)
                mx = fmaxf(mx, __shfl_xor_sync(0xffffffffu, mx, off));

            const float e0 = __expf(s[r][0] - mx);
            const float e1 = __expf(s[r][1] - mx);
            const float e2 = (lane < 4) ? __expf(s[r][2] - mx) : 0.0f;
            float sum = e0 + e1 + e2;
#pragma unroll
            for (int off = 16; off > 0; off >>= 1)
                sum += __shfl_xor_sync(0xffffffffu, sum, off);
            const float inv = 1.0f / sum;

            sp[warp][r][j0] = e0 * inv;
            sp[warp][r][j1] = e1 * inv;
            if (lane < 4) sp[warp][r][j2] = e2 * inv;
        }
        __syncwarp();

        // PV: lane owns d-pair (2*lane, 2*lane+1); packed accumulate over j
        u64 o2[4];
#pragma unroll
        for (int r = 0; r < 4; r++) o2[r] = 0ull;

#pragma unroll
        for (int j = 0; j < NTOK; j++) {
            const u64 vv = *reinterpret_cast<const u64*>(&sv2[j][2 * lane]);
            u64 pp0, pp1, pp2, pp3;
            DUP2(pp0, sp[warp][0][j]);
            DUP2(pp1, sp[warp][1][j]);
            DUP2(pp2, sp[warp][2][j]);
            DUP2(pp3, sp[warp][3][j]);
            FFMA2(o2[0], vv, pp0);
            FFMA2(o2[1], vv, pp1);
            FFMA2(o2[2], vv, pp2);
            FFMA2(o2[3], vv, pp3);
        }

#pragma unroll
        for (int r = 0; r < 4; r++) {
            float lo, hi;
            UNPACK2(lo, hi, o2[r]);
            const size_t obase = ((size_t)b * NTOK + row0 + r) * C_ + (size_t)h * HD;
            *reinterpret_cast<__half2*>(oa + obase + 2 * lane) =
                __half2(__float2half_rn(lo), __float2half_rn(hi));
        }
        __syncwarp();
    }
}

// ---------------------------------------------------------------------------
extern "C" void kernel_launch(void* const* d_in, const int* in_sizes, int n_in,
                              void* d_out, int out_size)
{
    const float* x      = (const float*)d_in[0];
    const float* pe     = (const float*)d_in[1];
    const float* mask   = (const float*)d_in[2];
    const float* w_qkv  = (const float*)d_in[3];
    const float* b_qkv  = (const float*)d_in[4];
    const float* w_proj = (const float*)d_in[5];
    const float* b_proj = (const float*)d_in[6];
    float* out = (float*)d_out;

    float* qkv_buf; cudaGetSymbolAddress((void**)&qkv_buf, g_qkv);
    __half *xa, *whi, *wlo, *phi, *plo, *aa;
    cudaGetSymbolAddress((void**)&xa,  g_xa);
    cudaGetSymbolAddress((void**)&whi, g_whi);
    cudaGetSymbolAddress((void**)&wlo, g_wlo);
    cudaGetSymbolAddress((void**)&phi, g_phi);
    cudaGetSymbolAddress((void**)&plo, g_plo);
    cudaGetSymbolAddress((void**)&aa,  g_aa);

    cudaFuncSetAttribute(gemm_f16x2_kernel,
                         cudaFuncAttributeMaxDynamicSharedMemorySize, GEMM_SMEM);

    // 0) precompute fp16 activations + split weights
    {
        const size_t nx = (size_t)M_ * C_ / 4;
        split_x_pe_f16<<<(unsigned)((nx + 255) / 256), 256>>>(x, pe, xa);
        const size_t nw = (size_t)K3C * C_;
        split_w_f16<<<(unsigned)((nw / 4 + 255) / 256), 256>>>(w_qkv, whi, wlo, nw);
        const size_t np = (size_t)C_ * C_;
        split_w_f16<<<(unsigned)((np / 4 + 255) / 256), 256>>>(w_proj, phi, plo, np);
    }

    // 1) QKV projection: (M x 768) @ (768 x 2304)^T + bias -> g_qkv (fp32)
    {
        const int NT = K3C / 128;           // 18
        const int TT = (M_ / 128) * NT;     // 9792
        gemm_f16x2_kernel<<<GEMM_GRID, 256, GEMM_SMEM>>>(
            xa, whi, wlo, b_qkv, qkv_buf, K3C, C_, NT, TT);
    }

    // 2) Attention -> fp16 output
    attention_kernel<<<B_ * H_, 256>>>(qkv_buf, mask, aa);

    // 3) Output projection -> d_out
    {
        const int NT = C_ / 128;            // 6
        const int TT = (M_ / 128) * NT;     // 4080
        gemm_f16x2_kernel<<<GEMM_GRID, 256, GEMM_SMEM>>>(
            aa, phi, plo, b_proj, out, C_, C_, NT, TT);
    }
}